// round 11
// baseline (speedup 1.0000x reference)
#include <cuda_runtime.h>
#include <cuda_bf16.h>
#include <math.h>
#include <float.h>
#include <stdint.h>

// Problem constants
#define B_GR   16
#define NP_    1024
#define FEAT_  512
#define HDIM   1024
#define E_TOT  262144        // 16*1024*16
#define NMAX   16384
#define K1_    820           // ceil(0.8*1024)
#define K2_    656           // ceil(0.8*820)
#define K3_    525           // ceil(0.8*656)
#define SLOT_LG 7            // 128 CSR slots per node (P(deg>127) ~ 1e-60)

// ---------------- device scratch (no allocation allowed) ----------------
__device__ __align__(16) float g_bufA[NMAX * HDIM];   // SAGE output (post-relu)
__device__ __align__(16) float g_bufB[NMAX * HDIM];   // pooled/gated features (fp32)
// bf16 split operand buffers for the MMA GEMM
__device__ __align__(16) __nv_bfloat16 g_ahi[NMAX * HDIM];   // mean-agg hi
__device__ __align__(16) __nv_bfloat16 g_alo[NMAX * HDIM];   // mean-agg lo
__device__ __align__(16) __nv_bfloat16 g_xhi[NMAX * HDIM];   // x / pooled hi
__device__ __align__(16) __nv_bfloat16 g_xlo[NMAX * HDIM];   // x / pooled lo
__device__ __align__(16) __nv_bfloat16 g_whi[2 * HDIM * HDIM];  // [Wl ; Wr] hi
__device__ __align__(16) __nv_bfloat16 g_wlo[2 * HDIM * HDIM];  // [Wl ; Wr] lo

__device__ int   g_src[E_TOT], g_dst[E_TOT], g_valid[E_TOT];
__device__ int   g_csr[NMAX << SLOT_LG];   // fixed-slot CSR: node*128 + pos
__device__ int   g_cnt[NMAX];
__device__ int   g_old[NMAX];
__device__ float g_vals[NMAX];
__device__ int   g_remap[NMAX];
__device__ float g_score[NMAX];

// ---------------- PTX helpers (all sm_80-level, no arch-variant features) --
static __device__ __forceinline__ uint32_t smem_u32(const void* p) {
    uint32_t a;
    asm("{ .reg .u64 t; cvta.to.shared.u64 t, %1; cvt.u32.u64 %0, t; }"
        : "=r"(a) : "l"(p));
    return a;
}

__device__ __forceinline__ void cpa16(uint32_t dst, const void* src, int szbytes) {
    asm volatile("cp.async.cg.shared.global [%0], [%1], 16, %2;"
                 :: "r"(dst), "l"(src), "r"(szbytes));
}
#define CP_COMMIT() asm volatile("cp.async.commit_group;" ::: "memory")
#define CP_WAIT2()  asm volatile("cp.async.wait_group 2;" ::: "memory")

#define LDSM_X4(R, addr) \
    asm volatile("ldmatrix.sync.aligned.m8n8.x4.shared.b16 {%0,%1,%2,%3}, [%4];" \
        : "=r"((R)[0]), "=r"((R)[1]), "=r"((R)[2]), "=r"((R)[3]) : "r"(addr))

#define MMA16816(C, A, B0, B1) \
    asm volatile("mma.sync.aligned.m16n8k16.row.col.f32.bf16.bf16.f32 " \
        "{%0,%1,%2,%3}, {%4,%5,%6,%7}, {%8,%9}, {%0,%1,%2,%3};" \
        : "+f"((C)[0]), "+f"((C)[1]), "+f"((C)[2]), "+f"((C)[3]) \
        : "r"((A)[0]), "r"((A)[1]), "r"((A)[2]), "r"((A)[3]), "r"(B0), "r"(B1))

// swizzled byte offset inside a tile with 64B (32 bf16) rows
__device__ __forceinline__ uint32_t sw64(int r, int c) {
    return (uint32_t)(r * 64 + ((c ^ ((r >> 1) & 3)) << 4));
}

// ---------------- GEMM smem layout ----------------
#define S_AH 0
#define S_AL 8192
#define S_BH 16384
#define S_BL 24576
#define STAGE_SZ 32768
#define NSTAGE 4
#define GEMM_SMEM (NSTAGE * STAGE_SZ)   // 128 KB, 4-stage ring

// ---------------- small utility kernels ----------------
__global__ void zero_cnt_kernel() {
    int i = blockIdx.x * 256 + threadIdx.x;
    if (i < NMAX) g_cnt[i] = 0;
}

__global__ void zero_out_kernel(float* out) {
    int i = blockIdx.x * 256 + threadIdx.x;
    out[i] = 0.0f;
}

// edge init fused with count + direct fixed-slot scatter (g_cnt zeroed first)
__global__ void edge_init_kernel(const int* __restrict__ ei) {
    int e = blockIdx.x * 256 + threadIdx.x;
    int s = ei[e];
    int d = ei[E_TOT + e];
    g_src[e] = s;
    g_dst[e] = d;
    g_valid[e] = 1;
    int pos = atomicAdd(&g_cnt[d], 1);
    g_csr[(d << SLOT_LG) + pos] = s;
}

// remap fused with count + direct scatter into the new graph's fixed-slot CSR
__global__ void edge_remap_kernel() {
    int e = blockIdx.x * 256 + threadIdx.x;
    if (!g_valid[e]) return;
    int s2 = g_remap[g_src[e]];
    int d2 = g_remap[g_dst[e]];
    if (s2 >= 0 && d2 >= 0) {
        g_src[e] = s2; g_dst[e] = d2;
        int pos = atomicAdd(&g_cnt[d2], 1);
        g_csr[(d2 << SLOT_LG) + pos] = s2;
    }
    else g_valid[e] = 0;
}

__device__ __forceinline__ void split_store(float v, __nv_bfloat16* hi, __nv_bfloat16* lo) {
    __nv_bfloat16 h = __float2bfloat16(v);
    *hi = h;
    *lo = __float2bfloat16(v - __bfloat162float(h));
}

// one block (256 threads) per dst node. float2 gathers: NP2 float2 per thread.
// Thread t covers elements {2t, 2t+1} (+ {512+2t, 512+2t+1} when NP2=2).
// 4-way edge unroll keeps 4*NP2 64B-segment loads in flight.
template <int NP2>
__global__ void aggregate_kernel(const float* __restrict__ xext, int sel, int F) {
    const float* __restrict__ xin = sel ? g_bufB : xext;
    int node = blockIdx.x;
    int c = g_cnt[node];
    int start = node << SLOT_LG;
    float2 acc[NP2];
#pragma unroll
    for (int i = 0; i < NP2; i++) { acc[i].x = 0.0f; acc[i].y = 0.0f; }
    int e = 0;
    for (; e + 3 < c; e += 4) {
        const float* r0 = xin + (size_t)g_csr[start + e + 0] * F;
        const float* r1 = xin + (size_t)g_csr[start + e + 1] * F;
        const float* r2 = xin + (size_t)g_csr[start + e + 2] * F;
        const float* r3 = xin + (size_t)g_csr[start + e + 3] * F;
        float2 v0[NP2], v1[NP2], v2[NP2], v3[NP2];
#pragma unroll
        for (int i = 0; i < NP2; i++) {
            int o = threadIdx.x * 2 + i * 512;
            v0[i] = *(const float2*)(r0 + o);
            v1[i] = *(const float2*)(r1 + o);
            v2[i] = *(const float2*)(r2 + o);
            v3[i] = *(const float2*)(r3 + o);
        }
#pragma unroll
        for (int i = 0; i < NP2; i++) {
            acc[i].x += (v0[i].x + v1[i].x) + (v2[i].x + v3[i].x);
            acc[i].y += (v0[i].y + v1[i].y) + (v2[i].y + v3[i].y);
        }
    }
    for (; e < c; e++) {
        const float* row = xin + (size_t)g_csr[start + e] * F;
#pragma unroll
        for (int i = 0; i < NP2; i++) {
            int o = threadIdx.x * 2 + i * 512;
            float2 v = *(const float2*)(row + o);
            acc[i].x += v.x; acc[i].y += v.y;
        }
    }
    float inv = 1.0f / (float)(c > 1 ? c : 1);
#pragma unroll
    for (int i = 0; i < NP2; i++) {
        size_t o = (size_t)node * F + threadIdx.x * 2 + i * 512;
        split_store(acc[i].x * inv, &g_ahi[o], &g_alo[o]);
        split_store(acc[i].y * inv, &g_ahi[o + 1], &g_alo[o + 1]);
    }
}

// fp32 -> bf16 hi/lo conversion, float4 per thread (n divisible by 1024)
__global__ void conv_kernel(const float* __restrict__ src,
                            __nv_bfloat16* __restrict__ hi,
                            __nv_bfloat16* __restrict__ lo, int n) {
    int i = (blockIdx.x * 256 + threadIdx.x) * 4;
    if (i < n) {
        float4 v = *(const float4*)(src + i);
        split_store(v.x, &hi[i + 0], &lo[i + 0]);
        split_store(v.y, &hi[i + 1], &lo[i + 1]);
        split_store(v.z, &hi[i + 2], &lo[i + 2]);
        split_store(v.w, &hi[i + 3], &lo[i + 3]);
    }
}

// ---------------- mma.sync fused SAGE GEMM (R4 config) ----------------
__global__ void __launch_bounds__(256, 1)
gemm_mma_kernel(int M, int K, const float* __restrict__ bias) {
    extern __shared__ char smem[];
    const uint32_t sbase = smem_u32(smem);
    const int tid  = threadIdx.x;
    const int lane = tid & 31;
    const int warp = tid >> 5;
    const int warpM = (warp & 3) * 32;
    const int warpN = (warp >> 2) * 64;
    const int row0 = blockIdx.x << 7;
    const int col0 = blockIdx.y << 7;

    const int nchunk = K >> 5;       // k32 chunks per operand source
    const int ntot = nchunk << 1;

    float C[2][8][4];
#pragma unroll
    for (int a = 0; a < 2; a++)
#pragma unroll
        for (int b = 0; b < 8; b++)
#pragma unroll
            for (int d = 0; d < 4; d++) C[a][b][d] = 0.0f;

    auto prefetch = [&](int i) {
        if (i < ntot) {
            int src = (i >= nchunk) ? 1 : 0;
            int k0 = (i - (src ? nchunk : 0)) << 5;
            const __nv_bfloat16* Ah = src ? g_xhi : g_ahi;
            const __nv_bfloat16* Al = src ? g_xlo : g_alo;
            const __nv_bfloat16* Bh = g_whi + (size_t)src * HDIM * K;
            const __nv_bfloat16* Bl = g_wlo + (size_t)src * HDIM * K;
            uint32_t sb = sbase + (uint32_t)(i % NSTAGE) * STAGE_SZ;
#pragma unroll
            for (int u = 0; u < 2; u++) {
                int q = tid + (u << 8);
                int r = q >> 2, c = q & 3;
                uint32_t so = sw64(r, c);
                int gr = row0 + r;
                int ok = (gr < M) ? 16 : 0;
                size_t gro = (size_t)(ok ? gr : 0) * K + k0 + (c << 3);
                cpa16(sb + S_AH + so, Ah + gro, ok);
                cpa16(sb + S_AL + so, Al + gro, ok);
                size_t gco = (size_t)(col0 + r) * K + k0 + (c << 3);
                cpa16(sb + S_BH + so, Bh + gco, 16);
                cpa16(sb + S_BL + so, Bl + gco, 16);
            }
        }
        CP_COMMIT();
    };

    prefetch(0);
    prefetch(1);
    prefetch(2);

    for (int i = 0; i < ntot; i++) {
        CP_WAIT2();
        __syncthreads();
        prefetch(i + 3);

        uint32_t sb = sbase + (uint32_t)(i % NSTAGE) * STAGE_SZ;
#pragma unroll
        for (int kk = 0; kk < 2; kk++) {
            uint32_t ah[2][4], al[2][4];
#pragma unroll
            for (int fm = 0; fm < 2; fm++) {
                int r = warpM + fm * 16 + (lane & 15);
                int c = (kk << 1) + (lane >> 4);
                uint32_t so = sw64(r, c);
                LDSM_X4(ah[fm], sb + S_AH + so);
                LDSM_X4(al[fm], sb + S_AL + so);
            }
            uint32_t bh[4][4], bl[4][4];
#pragma unroll
            for (int fn = 0; fn < 4; fn++) {
                int r = warpN + fn * 16 + ((lane >> 4) << 3) + (lane & 7);
                int c = (kk << 1) + ((lane >> 3) & 1);
                uint32_t so = sw64(r, c);
                LDSM_X4(bh[fn], sb + S_BH + so);
                LDSM_X4(bl[fn], sb + S_BL + so);
            }
#pragma unroll
            for (int t = 0; t < 3; t++) {
#pragma unroll
                for (int fm = 0; fm < 2; fm++)
#pragma unroll
                    for (int fn = 0; fn < 4; fn++)
#pragma unroll
                        for (int g = 0; g < 2; g++) {
                            float* Cp = C[fm][fn * 2 + g];
                            const uint32_t* A = (t == 2) ? al[fm] : ah[fm];
                            const uint32_t* Bq = (t == 1) ? bl[fn] : bh[fn];
                            MMA16816(Cp, A, Bq[g * 2], Bq[g * 2 + 1]);
                        }
            }
        }
    }

    // ---- epilogue: bias + relu, direct stores ----
#pragma unroll
    for (int fm = 0; fm < 2; fm++)
#pragma unroll
        for (int fn = 0; fn < 4; fn++)
#pragma unroll
            for (int g = 0; g < 2; g++) {
                int rb = row0 + warpM + fm * 16 + (lane >> 2);
                int col = col0 + warpN + fn * 16 + g * 8 + ((lane & 3) << 1);
                float2 bb = *(const float2*)(bias + col);
                float* Cp = C[fm][fn * 2 + g];
                if (rb < M) {
                    float2 v;
                    v.x = fmaxf(Cp[0] + bb.x, 0.0f);
                    v.y = fmaxf(Cp[1] + bb.y, 0.0f);
                    *(float2*)(g_bufA + (size_t)rb * HDIM + col) = v;
                }
                if (rb + 8 < M) {
                    float2 v;
                    v.x = fmaxf(Cp[2] + bb.x, 0.0f);
                    v.y = fmaxf(Cp[3] + bb.y, 0.0f);
                    *(float2*)(g_bufA + (size_t)(rb + 8) * HDIM + col) = v;
                }
            }
}

// ---------------- scoring / top-k / pooling ----------------
// one warp per node: s = tanh((h . p)/||p||); ||p|| computed per block (fused)
// float4 loads: 8 iterations per lane.
__global__ void score_kernel(const float* __restrict__ p, int N) {
    __shared__ float sh[8];
    __shared__ float spn;
    int tid = threadIdx.x;
    int lane = tid & 31, wid = tid >> 5;
    float s = 0.0f;
#pragma unroll
    for (int i = tid; i < HDIM; i += 256) s += p[i] * p[i];
#pragma unroll
    for (int o = 16; o; o >>= 1) s += __shfl_xor_sync(0xffffffffu, s, o);
    if (lane == 0) sh[wid] = s;
    __syncthreads();
    if (tid == 0) {
        float t = 0.0f;
#pragma unroll
        for (int i = 0; i < 8; i++) t += sh[i];
        spn = sqrtf(t);
    }
    __syncthreads();

    int node = blockIdx.x * 8 + wid;
    if (node >= N) return;
    const float* row = g_bufA + (size_t)node * HDIM;
    float acc = 0.0f;
#pragma unroll
    for (int i = lane * 4; i < HDIM; i += 128) {
        float4 a = *(const float4*)(row + i);
        float4 b = *(const float4*)(p + i);
        acc += a.x * b.x + a.y * b.y + a.z * b.z + a.w * b.w;
    }
#pragma unroll
    for (int o = 16; o; o >>= 1) acc += __shfl_xor_sync(0xffffffffu, acc, o);
    if (lane == 0) g_score[node] = tanhf(acc / spn);
}

// one block per graph: bitonic sort 1024 (score,idx) pairs descending
__global__ void topk_kernel(int n_per, int k) {
    __shared__ float ss[1024];
    __shared__ int si[1024];
    int g = blockIdx.x;
    int tid = threadIdx.x;  // 512 threads
    for (int i = tid; i < 1024; i += 512) {
        if (i < n_per) { ss[i] = g_score[g * n_per + i]; si[i] = i; }
        else           { ss[i] = -FLT_MAX;               si[i] = i; }
    }
    __syncthreads();
    for (int ksz = 2; ksz <= 1024; ksz <<= 1) {
        for (int j = ksz >> 1; j > 0; j >>= 1) {
            for (int i = tid; i < 1024; i += 512) {
                int ixj = i ^ j;
                if (ixj > i) {
                    bool dirDesc = ((i & ksz) == 0);
                    float a = ss[i], b = ss[ixj];
                    bool doswap = dirDesc ? (a < b) : (a > b);
                    if (doswap) {
                        ss[i] = b; ss[ixj] = a;
                        int tpi = si[i]; si[i] = si[ixj]; si[ixj] = tpi;
                    }
                }
            }
            __syncthreads();
        }
    }
    for (int r = tid; r < n_per; r += 512) {
        int oldLocal = si[r];
        if (r < k) {
            g_old[g * k + r]  = g * n_per + oldLocal;
            g_vals[g * k + r] = ss[r];
            g_remap[g * n_per + oldLocal] = g * k + r;
        } else {
            g_remap[g * n_per + oldLocal] = -1;
        }
    }
}

// new node i <- old node * score; writes fp32 bufB + bf16 hi/lo for next GEMM
// float2 per thread per half-row.
__global__ void gate_kernel() {
    int i = blockIdx.x;
    int old = g_old[i];
    float v = g_vals[i];
    const float* srcp = g_bufA + (size_t)old * HDIM;
#pragma unroll
    for (int h = 0; h < 2; h++) {
        int f = threadIdx.x * 2 + h * 512;
        float2 val = *(const float2*)(srcp + f);
        val.x *= v; val.y *= v;
        *(float2*)(g_bufB + (size_t)i * HDIM + f) = val;
        split_store(val.x, &g_xhi[(size_t)i * HDIM + f], &g_xlo[(size_t)i * HDIM + f]);
        split_store(val.y, &g_xhi[(size_t)i * HDIM + f + 1], &g_xlo[(size_t)i * HDIM + f + 1]);
    }
}

// out[g, 0:1024] += col-max, out[g, 1024:2048] += col-mean (over bufB), 4-way unroll
__global__ void readout_kernel(float* __restrict__ out, int nper) {
    int gid = blockIdx.x * 256 + threadIdx.x;  // < B*1024
    int g = gid >> 10, f = gid & 1023;
    const float* base = g_bufB + (size_t)g * nper * HDIM + f;
    float mx = -FLT_MAX, sm = 0.0f;
    int i = 0;
    for (; i + 3 < nper; i += 4) {
        float v0 = base[(size_t)(i + 0) * HDIM];
        float v1 = base[(size_t)(i + 1) * HDIM];
        float v2 = base[(size_t)(i + 2) * HDIM];
        float v3 = base[(size_t)(i + 3) * HDIM];
        mx = fmaxf(mx, fmaxf(fmaxf(v0, v1), fmaxf(v2, v3)));
        sm += (v0 + v1) + (v2 + v3);
    }
    for (; i < nper; i++) {
        float v = base[(size_t)i * HDIM];
        mx = fmaxf(mx, v);
        sm += v;
    }
    out[g * 2048 + f] += mx;
    out[g * 2048 + 1024 + f] += sm / (float)nper;
}

// ---------------- host orchestration ----------------
static void launch_gemm(int M, int K, const float* bias) {
    dim3 grid((M + 127) >> 7, HDIM / 128);
    gemm_mma_kernel<<<grid, 256, GEMM_SMEM>>>(M, K, bias);
}

extern "C" void kernel_launch(void* const* d_in, const int* in_sizes, int n_in,
                              void* d_out, int out_size) {
    const float* x  = (const float*)d_in[0];
    const int*   ei = (const int*)d_in[1];
    const float* W1l = (const float*)d_in[3];
    const float* b1  = (const float*)d_in[4];
    const float* W1r = (const float*)d_in[5];
    const float* p1  = (const float*)d_in[6];
    const float* W2l = (const float*)d_in[7];
    const float* b2  = (const float*)d_in[8];
    const float* W2r = (const float*)d_in[9];
    const float* p2  = (const float*)d_in[10];
    const float* W3l = (const float*)d_in[11];
    const float* b3  = (const float*)d_in[12];
    const float* W3r = (const float*)d_in[13];
    const float* p3  = (const float*)d_in[14];
    float* out = (float*)d_out;

    static int s_attr_done = 0;
    if (!s_attr_done) {
        cudaFuncSetAttribute(gemm_mma_kernel,
                             cudaFuncAttributeMaxDynamicSharedMemorySize, GEMM_SMEM);
        s_attr_done = 1;
    }

    const int N1 = B_GR * NP_;   // 16384
    const int N2 = B_GR * K1_;   // 13120
    const int N3 = B_GR * K2_;   // 10496

    __nv_bfloat16 *whi = nullptr, *wlo = nullptr;
    cudaGetSymbolAddress((void**)&whi, g_whi);
    cudaGetSymbolAddress((void**)&wlo, g_wlo);
    __nv_bfloat16 *xhi = nullptr, *xlo = nullptr;
    cudaGetSymbolAddress((void**)&xhi, g_xhi);
    cudaGetSymbolAddress((void**)&xlo, g_xlo);

    zero_out_kernel<<<(B_GR * 2 * HDIM) / 256, 256>>>(out);

    // ---------- layer 1 (K = 512) ----------
    zero_cnt_kernel<<<NMAX / 256, 256>>>();
    edge_init_kernel<<<E_TOT / 256, 256>>>(ei);   // init + count + scatter
    aggregate_kernel<1><<<N1, 256>>>(x, 0, FEAT_);
    conv_kernel<<<(N1 * FEAT_) / 1024, 256>>>(x, xhi, xlo, N1 * FEAT_);
    conv_kernel<<<(HDIM * FEAT_) / 1024, 256>>>(W1l, whi, wlo, HDIM * FEAT_);
    conv_kernel<<<(HDIM * FEAT_) / 1024, 256>>>(W1r, whi + HDIM * FEAT_, wlo + HDIM * FEAT_,
                                                HDIM * FEAT_);
    launch_gemm(N1, FEAT_, b1);
    score_kernel<<<N1 / 8, 256>>>(p1, N1);
    topk_kernel<<<B_GR, 512>>>(NP_, K1_);
    gate_kernel<<<N2, 256>>>();
    zero_cnt_kernel<<<NMAX / 256, 256>>>();
    edge_remap_kernel<<<E_TOT / 256, 256>>>();    // remap + count + scatter
    readout_kernel<<<(B_GR * HDIM) / 256, 256>>>(out, K1_);

    // ---------- layer 2 (K = 1024) ----------
    aggregate_kernel<2><<<N2, 256>>>(nullptr, 1, HDIM);
    conv_kernel<<<(HDIM * HDIM) / 1024, 256>>>(W2l, whi, wlo, HDIM * HDIM);
    conv_kernel<<<(HDIM * HDIM) / 1024, 256>>>(W2r, whi + HDIM * HDIM, wlo + HDIM * HDIM,
                                               HDIM * HDIM);
    launch_gemm(N2, HDIM, b2);
    score_kernel<<<(N2 + 7) / 8, 256>>>(p2, N2);
    topk_kernel<<<B_GR, 512>>>(K1_, K2_);
    gate_kernel<<<N3, 256>>>();
    zero_cnt_kernel<<<NMAX / 256, 256>>>();
    edge_remap_kernel<<<E_TOT / 256, 256>>>();    // remap + count + scatter
    readout_kernel<<<(B_GR * HDIM) / 256, 256>>>(out, K2_);

    // ---------- layer 3 (K = 1024) ----------
    aggregate_kernel<2><<<N3, 256>>>(nullptr, 1, HDIM);
    conv_kernel<<<(HDIM * HDIM) / 1024, 256>>>(W3l, whi, wlo, HDIM * HDIM);
    conv_kernel<<<(HDIM * HDIM) / 1024, 256>>>(W3r, whi + HDIM * HDIM, wlo + HDIM * HDIM,
                                               HDIM * HDIM);
    launch_gemm(N3, HDIM, b3);
    score_kernel<<<(N3 + 7) / 8, 256>>>(p3, N3);
    topk_kernel<<<B_GR, 512>>>(K2_, K3_);
    gate_kernel<<<B_GR * K3_, 256>>>();
    readout_kernel<<<(B_GR * HDIM) / 256, 256>>>(out, K3_);
}

// round 12
// speedup vs baseline: 1.0001x; 1.0001x over previous
#include <cuda_runtime.h>
#include <cuda_bf16.h>
#include <math.h>
#include <float.h>
#include <stdint.h>

// Problem constants
#define B_GR   16
#define NP_    1024
#define FEAT_  512
#define HDIM   1024
#define E_TOT  262144        // 16*1024*16
#define NMAX   16384
#define K1_    820           // ceil(0.8*1024)
#define K2_    656           // ceil(0.8*820)
#define K3_    525           // ceil(0.8*656)
#define SLOT_LG 7            // 128 CSR slots per node (P(deg>127) ~ 1e-60)

// ---------------- device scratch (no allocation allowed) ----------------
__device__ __align__(16) float g_bufA[NMAX * HDIM];   // SAGE output (post-relu)
__device__ __align__(16) float g_bufB[NMAX * HDIM];   // pooled/gated features (fp32)
// bf16 split operand buffers for the MMA GEMM
__device__ __align__(16) __nv_bfloat16 g_ahi[NMAX * HDIM];   // mean-agg hi
__device__ __align__(16) __nv_bfloat16 g_alo[NMAX * HDIM];   // mean-agg lo
__device__ __align__(16) __nv_bfloat16 g_xhi[NMAX * HDIM];   // x / pooled hi
__device__ __align__(16) __nv_bfloat16 g_xlo[NMAX * HDIM];   // x / pooled lo
__device__ __align__(16) __nv_bfloat16 g_whi[2 * HDIM * HDIM];  // [Wl ; Wr] hi
__device__ __align__(16) __nv_bfloat16 g_wlo[2 * HDIM * HDIM];  // [Wl ; Wr] lo

__device__ int   g_src[E_TOT], g_dst[E_TOT], g_valid[E_TOT];
__device__ int   g_csr[NMAX << SLOT_LG];   // fixed-slot CSR: node*128 + pos
__device__ int   g_cnt[NMAX];
__device__ int   g_old[NMAX];
__device__ float g_vals[NMAX];
__device__ int   g_remap[NMAX];
__device__ float g_score[NMAX];

// ---------------- PTX helpers (all sm_80-level, no arch-variant features) --
static __device__ __forceinline__ uint32_t smem_u32(const void* p) {
    uint32_t a;
    asm("{ .reg .u64 t; cvta.to.shared.u64 t, %1; cvt.u32.u64 %0, t; }"
        : "=r"(a) : "l"(p));
    return a;
}

__device__ __forceinline__ void cpa16(uint32_t dst, const void* src, int szbytes) {
    asm volatile("cp.async.cg.shared.global [%0], [%1], 16, %2;"
                 :: "r"(dst), "l"(src), "r"(szbytes));
}
#define CP_COMMIT() asm volatile("cp.async.commit_group;" ::: "memory")
#define CP_WAIT2()  asm volatile("cp.async.wait_group 2;" ::: "memory")

#define LDSM_X4(R, addr) \
    asm volatile("ldmatrix.sync.aligned.m8n8.x4.shared.b16 {%0,%1,%2,%3}, [%4];" \
        : "=r"((R)[0]), "=r"((R)[1]), "=r"((R)[2]), "=r"((R)[3]) : "r"(addr))

#define MMA16816(C, A, B0, B1) \
    asm volatile("mma.sync.aligned.m16n8k16.row.col.f32.bf16.bf16.f32 " \
        "{%0,%1,%2,%3}, {%4,%5,%6,%7}, {%8,%9}, {%0,%1,%2,%3};" \
        : "+f"((C)[0]), "+f"((C)[1]), "+f"((C)[2]), "+f"((C)[3]) \
        : "r"((A)[0]), "r"((A)[1]), "r"((A)[2]), "r"((A)[3]), "r"(B0), "r"(B1))

// swizzled byte offset inside a tile with 64B (32 bf16) rows
__device__ __forceinline__ uint32_t sw64(int r, int c) {
    return (uint32_t)(r * 64 + ((c ^ ((r >> 1) & 3)) << 4));
}

// ---------------- GEMM smem layout ----------------
#define S_AH 0
#define S_AL 8192
#define S_BH 16384
#define S_BL 24576
#define STAGE_SZ 32768
#define NSTAGE 4
#define GEMM_SMEM (NSTAGE * STAGE_SZ)   // 128 KB, 4-stage ring

// ---------------- small utility kernels ----------------
__global__ void zero_cnt_kernel() {
    int i = blockIdx.x * 256 + threadIdx.x;
    if (i < NMAX) g_cnt[i] = 0;
}

__global__ void zero_out_kernel(float* out) {
    int i = blockIdx.x * 256 + threadIdx.x;
    out[i] = 0.0f;
}

// edge init fused with count + direct fixed-slot scatter (g_cnt zeroed first)
__global__ void edge_init_kernel(const int* __restrict__ ei) {
    int e = blockIdx.x * 256 + threadIdx.x;
    int s = ei[e];
    int d = ei[E_TOT + e];
    g_src[e] = s;
    g_dst[e] = d;
    g_valid[e] = 1;
    int pos = atomicAdd(&g_cnt[d], 1);
    g_csr[(d << SLOT_LG) + pos] = s;
}

// remap fused with count + direct scatter into the new graph's fixed-slot CSR
__global__ void edge_remap_kernel() {
    int e = blockIdx.x * 256 + threadIdx.x;
    if (!g_valid[e]) return;
    int s2 = g_remap[g_src[e]];
    int d2 = g_remap[g_dst[e]];
    if (s2 >= 0 && d2 >= 0) {
        g_src[e] = s2; g_dst[e] = d2;
        int pos = atomicAdd(&g_cnt[d2], 1);
        g_csr[(d2 << SLOT_LG) + pos] = s2;
    }
    else g_valid[e] = 0;
}

__device__ __forceinline__ void split_store(float v, __nv_bfloat16* hi, __nv_bfloat16* lo) {
    __nv_bfloat16 h = __float2bfloat16(v);
    *hi = h;
    *lo = __float2bfloat16(v - __bfloat162float(h));
}

// one block (256 threads) per dst node; NF = F/256. Scalar strided loads
// (R10 measured-best: 32 regs, 91% occupancy). 4-way edge unroll for MLP.
template <int NF>
__global__ void aggregate_kernel(const float* __restrict__ xext, int sel, int F) {
    const float* __restrict__ xin = sel ? g_bufB : xext;
    int node = blockIdx.x;
    int c = g_cnt[node];
    int start = node << SLOT_LG;
    float acc[NF];
#pragma unroll
    for (int i = 0; i < NF; i++) acc[i] = 0.0f;
    int e = 0;
    for (; e + 3 < c; e += 4) {
        const float* r0 = xin + (size_t)g_csr[start + e + 0] * F;
        const float* r1 = xin + (size_t)g_csr[start + e + 1] * F;
        const float* r2 = xin + (size_t)g_csr[start + e + 2] * F;
        const float* r3 = xin + (size_t)g_csr[start + e + 3] * F;
        float v0[NF], v1[NF], v2[NF], v3[NF];
#pragma unroll
        for (int i = 0; i < NF; i++) {
            int o = threadIdx.x + i * 256;
            v0[i] = r0[o]; v1[i] = r1[o]; v2[i] = r2[o]; v3[i] = r3[o];
        }
#pragma unroll
        for (int i = 0; i < NF; i++) acc[i] += (v0[i] + v1[i]) + (v2[i] + v3[i]);
    }
    for (; e < c; e++) {
        const float* row = xin + (size_t)g_csr[start + e] * F;
#pragma unroll
        for (int i = 0; i < NF; i++) acc[i] += row[threadIdx.x + i * 256];
    }
    float inv = 1.0f / (float)(c > 1 ? c : 1);
#pragma unroll
    for (int i = 0; i < NF; i++) {
        size_t o = (size_t)node * F + threadIdx.x + i * 256;
        split_store(acc[i] * inv, &g_ahi[o], &g_alo[o]);
    }
}

// fp32 -> bf16 hi/lo conversion, float4 per thread (n divisible by 1024)
__global__ void conv_kernel(const float* __restrict__ src,
                            __nv_bfloat16* __restrict__ hi,
                            __nv_bfloat16* __restrict__ lo, int n) {
    int i = (blockIdx.x * 256 + threadIdx.x) * 4;
    if (i < n) {
        float4 v = *(const float4*)(src + i);
        split_store(v.x, &hi[i + 0], &lo[i + 0]);
        split_store(v.y, &hi[i + 1], &lo[i + 1]);
        split_store(v.z, &hi[i + 2], &lo[i + 2]);
        split_store(v.w, &hi[i + 3], &lo[i + 3]);
    }
}

// ---------------- mma.sync fused SAGE GEMM (R4 config) ----------------
__global__ void __launch_bounds__(256, 1)
gemm_mma_kernel(int M, int K, const float* __restrict__ bias) {
    extern __shared__ char smem[];
    const uint32_t sbase = smem_u32(smem);
    const int tid  = threadIdx.x;
    const int lane = tid & 31;
    const int warp = tid >> 5;
    const int warpM = (warp & 3) * 32;
    const int warpN = (warp >> 2) * 64;
    const int row0 = blockIdx.x << 7;
    const int col0 = blockIdx.y << 7;

    const int nchunk = K >> 5;       // k32 chunks per operand source
    const int ntot = nchunk << 1;

    float C[2][8][4];
#pragma unroll
    for (int a = 0; a < 2; a++)
#pragma unroll
        for (int b = 0; b < 8; b++)
#pragma unroll
            for (int d = 0; d < 4; d++) C[a][b][d] = 0.0f;

    auto prefetch = [&](int i) {
        if (i < ntot) {
            int src = (i >= nchunk) ? 1 : 0;
            int k0 = (i - (src ? nchunk : 0)) << 5;
            const __nv_bfloat16* Ah = src ? g_xhi : g_ahi;
            const __nv_bfloat16* Al = src ? g_xlo : g_alo;
            const __nv_bfloat16* Bh = g_whi + (size_t)src * HDIM * K;
            const __nv_bfloat16* Bl = g_wlo + (size_t)src * HDIM * K;
            uint32_t sb = sbase + (uint32_t)(i % NSTAGE) * STAGE_SZ;
#pragma unroll
            for (int u = 0; u < 2; u++) {
                int q = tid + (u << 8);
                int r = q >> 2, c = q & 3;
                uint32_t so = sw64(r, c);
                int gr = row0 + r;
                int ok = (gr < M) ? 16 : 0;
                size_t gro = (size_t)(ok ? gr : 0) * K + k0 + (c << 3);
                cpa16(sb + S_AH + so, Ah + gro, ok);
                cpa16(sb + S_AL + so, Al + gro, ok);
                size_t gco = (size_t)(col0 + r) * K + k0 + (c << 3);
                cpa16(sb + S_BH + so, Bh + gco, 16);
                cpa16(sb + S_BL + so, Bl + gco, 16);
            }
        }
        CP_COMMIT();
    };

    prefetch(0);
    prefetch(1);
    prefetch(2);

    for (int i = 0; i < ntot; i++) {
        CP_WAIT2();
        __syncthreads();
        prefetch(i + 3);

        uint32_t sb = sbase + (uint32_t)(i % NSTAGE) * STAGE_SZ;
#pragma unroll
        for (int kk = 0; kk < 2; kk++) {
            uint32_t ah[2][4], al[2][4];
#pragma unroll
            for (int fm = 0; fm < 2; fm++) {
                int r = warpM + fm * 16 + (lane & 15);
                int c = (kk << 1) + (lane >> 4);
                uint32_t so = sw64(r, c);
                LDSM_X4(ah[fm], sb + S_AH + so);
                LDSM_X4(al[fm], sb + S_AL + so);
            }
            uint32_t bh[4][4], bl[4][4];
#pragma unroll
            for (int fn = 0; fn < 4; fn++) {
                int r = warpN + fn * 16 + ((lane >> 4) << 3) + (lane & 7);
                int c = (kk << 1) + ((lane >> 3) & 1);
                uint32_t so = sw64(r, c);
                LDSM_X4(bh[fn], sb + S_BH + so);
                LDSM_X4(bl[fn], sb + S_BL + so);
            }
#pragma unroll
            for (int t = 0; t < 3; t++) {
#pragma unroll
                for (int fm = 0; fm < 2; fm++)
#pragma unroll
                    for (int fn = 0; fn < 4; fn++)
#pragma unroll
                        for (int g = 0; g < 2; g++) {
                            float* Cp = C[fm][fn * 2 + g];
                            const uint32_t* A = (t == 2) ? al[fm] : ah[fm];
                            const uint32_t* Bq = (t == 1) ? bl[fn] : bh[fn];
                            MMA16816(Cp, A, Bq[g * 2], Bq[g * 2 + 1]);
                        }
            }
        }
    }

    // ---- epilogue: bias + relu, direct stores ----
#pragma unroll
    for (int fm = 0; fm < 2; fm++)
#pragma unroll
        for (int fn = 0; fn < 4; fn++)
#pragma unroll
            for (int g = 0; g < 2; g++) {
                int rb = row0 + warpM + fm * 16 + (lane >> 2);
                int col = col0 + warpN + fn * 16 + g * 8 + ((lane & 3) << 1);
                float2 bb = *(const float2*)(bias + col);
                float* Cp = C[fm][fn * 2 + g];
                if (rb < M) {
                    float2 v;
                    v.x = fmaxf(Cp[0] + bb.x, 0.0f);
                    v.y = fmaxf(Cp[1] + bb.y, 0.0f);
                    *(float2*)(g_bufA + (size_t)rb * HDIM + col) = v;
                }
                if (rb + 8 < M) {
                    float2 v;
                    v.x = fmaxf(Cp[2] + bb.x, 0.0f);
                    v.y = fmaxf(Cp[3] + bb.y, 0.0f);
                    *(float2*)(g_bufA + (size_t)(rb + 8) * HDIM + col) = v;
                }
            }
}

// ---------------- scoring / top-k / pooling ----------------
// one warp per node: s = tanh((h . p)/||p||); ||p|| computed per block (fused)
// float4 loads: 8 iterations per lane.
__global__ void score_kernel(const float* __restrict__ p, int N) {
    __shared__ float sh[8];
    __shared__ float spn;
    int tid = threadIdx.x;
    int lane = tid & 31, wid = tid >> 5;
    float s = 0.0f;
#pragma unroll
    for (int i = tid; i < HDIM; i += 256) s += p[i] * p[i];
#pragma unroll
    for (int o = 16; o; o >>= 1) s += __shfl_xor_sync(0xffffffffu, s, o);
    if (lane == 0) sh[wid] = s;
    __syncthreads();
    if (tid == 0) {
        float t = 0.0f;
#pragma unroll
        for (int i = 0; i < 8; i++) t += sh[i];
        spn = sqrtf(t);
    }
    __syncthreads();

    int node = blockIdx.x * 8 + wid;
    if (node >= N) return;
    const float* row = g_bufA + (size_t)node * HDIM;
    float acc = 0.0f;
#pragma unroll
    for (int i = lane * 4; i < HDIM; i += 128) {
        float4 a = *(const float4*)(row + i);
        float4 b = *(const float4*)(p + i);
        acc += a.x * b.x + a.y * b.y + a.z * b.z + a.w * b.w;
    }
#pragma unroll
    for (int o = 16; o; o >>= 1) acc += __shfl_xor_sync(0xffffffffu, acc, o);
    if (lane == 0) g_score[node] = tanhf(acc / spn);
}

// one block per graph: bitonic sort 1024 (score,idx) pairs descending
__global__ void topk_kernel(int n_per, int k) {
    __shared__ float ss[1024];
    __shared__ int si[1024];
    int g = blockIdx.x;
    int tid = threadIdx.x;  // 512 threads
    for (int i = tid; i < 1024; i += 512) {
        if (i < n_per) { ss[i] = g_score[g * n_per + i]; si[i] = i; }
        else           { ss[i] = -FLT_MAX;               si[i] = i; }
    }
    __syncthreads();
    for (int ksz = 2; ksz <= 1024; ksz <<= 1) {
        for (int j = ksz >> 1; j > 0; j >>= 1) {
            for (int i = tid; i < 1024; i += 512) {
                int ixj = i ^ j;
                if (ixj > i) {
                    bool dirDesc = ((i & ksz) == 0);
                    float a = ss[i], b = ss[ixj];
                    bool doswap = dirDesc ? (a < b) : (a > b);
                    if (doswap) {
                        ss[i] = b; ss[ixj] = a;
                        int tpi = si[i]; si[i] = si[ixj]; si[ixj] = tpi;
                    }
                }
            }
            __syncthreads();
        }
    }
    for (int r = tid; r < n_per; r += 512) {
        int oldLocal = si[r];
        if (r < k) {
            g_old[g * k + r]  = g * n_per + oldLocal;
            g_vals[g * k + r] = ss[r];
            g_remap[g * n_per + oldLocal] = g * k + r;
        } else {
            g_remap[g * n_per + oldLocal] = -1;
        }
    }
}

// new node i <- old node * score; writes fp32 bufB + bf16 hi/lo for next GEMM
// float2 per thread per half-row.
__global__ void gate_kernel() {
    int i = blockIdx.x;
    int old = g_old[i];
    float v = g_vals[i];
    const float* srcp = g_bufA + (size_t)old * HDIM;
#pragma unroll
    for (int h = 0; h < 2; h++) {
        int f = threadIdx.x * 2 + h * 512;
        float2 val = *(const float2*)(srcp + f);
        val.x *= v; val.y *= v;
        *(float2*)(g_bufB + (size_t)i * HDIM + f) = val;
        split_store(val.x, &g_xhi[(size_t)i * HDIM + f], &g_xlo[(size_t)i * HDIM + f]);
        split_store(val.y, &g_xhi[(size_t)i * HDIM + f + 1], &g_xlo[(size_t)i * HDIM + f + 1]);
    }
}

// out[g, 0:1024] += col-max, out[g, 1024:2048] += col-mean (over bufB), 4-way unroll
__global__ void readout_kernel(float* __restrict__ out, int nper) {
    int gid = blockIdx.x * 256 + threadIdx.x;  // < B*1024
    int g = gid >> 10, f = gid & 1023;
    const float* base = g_bufB + (size_t)g * nper * HDIM + f;
    float mx = -FLT_MAX, sm = 0.0f;
    int i = 0;
    for (; i + 3 < nper; i += 4) {
        float v0 = base[(size_t)(i + 0) * HDIM];
        float v1 = base[(size_t)(i + 1) * HDIM];
        float v2 = base[(size_t)(i + 2) * HDIM];
        float v3 = base[(size_t)(i + 3) * HDIM];
        mx = fmaxf(mx, fmaxf(fmaxf(v0, v1), fmaxf(v2, v3)));
        sm += (v0 + v1) + (v2 + v3);
    }
    for (; i < nper; i++) {
        float v = base[(size_t)i * HDIM];
        mx = fmaxf(mx, v);
        sm += v;
    }
    out[g * 2048 + f] += mx;
    out[g * 2048 + 1024 + f] += sm / (float)nper;
}

// ---------------- host orchestration ----------------
static void launch_gemm(int M, int K, const float* bias) {
    dim3 grid((M + 127) >> 7, HDIM / 128);
    gemm_mma_kernel<<<grid, 256, GEMM_SMEM>>>(M, K, bias);
}

extern "C" void kernel_launch(void* const* d_in, const int* in_sizes, int n_in,
                              void* d_out, int out_size) {
    const float* x  = (const float*)d_in[0];
    const int*   ei = (const int*)d_in[1];
    const float* W1l = (const float*)d_in[3];
    const float* b1  = (const float*)d_in[4];
    const float* W1r = (const float*)d_in[5];
    const float* p1  = (const float*)d_in[6];
    const float* W2l = (const float*)d_in[7];
    const float* b2  = (const float*)d_in[8];
    const float* W2r = (const float*)d_in[9];
    const float* p2  = (const float*)d_in[10];
    const float* W3l = (const float*)d_in[11];
    const float* b3  = (const float*)d_in[12];
    const float* W3r = (const float*)d_in[13];
    const float* p3  = (const float*)d_in[14];
    float* out = (float*)d_out;

    static int s_attr_done = 0;
    if (!s_attr_done) {
        cudaFuncSetAttribute(gemm_mma_kernel,
                             cudaFuncAttributeMaxDynamicSharedMemorySize, GEMM_SMEM);
        s_attr_done = 1;
    }

    const int N1 = B_GR * NP_;   // 16384
    const int N2 = B_GR * K1_;   // 13120
    const int N3 = B_GR * K2_;   // 10496

    __nv_bfloat16 *whi = nullptr, *wlo = nullptr;
    cudaGetSymbolAddress((void**)&whi, g_whi);
    cudaGetSymbolAddress((void**)&wlo, g_wlo);
    __nv_bfloat16 *xhi = nullptr, *xlo = nullptr;
    cudaGetSymbolAddress((void**)&xhi, g_xhi);
    cudaGetSymbolAddress((void**)&xlo, g_xlo);

    zero_out_kernel<<<(B_GR * 2 * HDIM) / 256, 256>>>(out);

    // ---------- layer 1 (K = 512) ----------
    zero_cnt_kernel<<<NMAX / 256, 256>>>();
    edge_init_kernel<<<E_TOT / 256, 256>>>(ei);   // init + count + scatter
    aggregate_kernel<2><<<N1, 256>>>(x, 0, FEAT_);
    conv_kernel<<<(N1 * FEAT_) / 1024, 256>>>(x, xhi, xlo, N1 * FEAT_);
    conv_kernel<<<(HDIM * FEAT_) / 1024, 256>>>(W1l, whi, wlo, HDIM * FEAT_);
    conv_kernel<<<(HDIM * FEAT_) / 1024, 256>>>(W1r, whi + HDIM * FEAT_, wlo + HDIM * FEAT_,
                                                HDIM * FEAT_);
    launch_gemm(N1, FEAT_, b1);
    score_kernel<<<N1 / 8, 256>>>(p1, N1);
    topk_kernel<<<B_GR, 512>>>(NP_, K1_);
    gate_kernel<<<N2, 256>>>();
    zero_cnt_kernel<<<NMAX / 256, 256>>>();
    edge_remap_kernel<<<E_TOT / 256, 256>>>();    // remap + count + scatter
    readout_kernel<<<(B_GR * HDIM) / 256, 256>>>(out, K1_);

    // ---------- layer 2 (K = 1024) ----------
    aggregate_kernel<4><<<N2, 256>>>(nullptr, 1, HDIM);
    conv_kernel<<<(HDIM * HDIM) / 1024, 256>>>(W2l, whi, wlo, HDIM * HDIM);
    conv_kernel<<<(HDIM * HDIM) / 1024, 256>>>(W2r, whi + HDIM * HDIM, wlo + HDIM * HDIM,
                                               HDIM * HDIM);
    launch_gemm(N2, HDIM, b2);
    score_kernel<<<(N2 + 7) / 8, 256>>>(p2, N2);
    topk_kernel<<<B_GR, 512>>>(K1_, K2_);
    gate_kernel<<<N3, 256>>>();
    zero_cnt_kernel<<<NMAX / 256, 256>>>();
    edge_remap_kernel<<<E_TOT / 256, 256>>>();    // remap + count + scatter
    readout_kernel<<<(B_GR * HDIM) / 256, 256>>>(out, K2_);

    // ---------- layer 3 (K = 1024) ----------
    aggregate_kernel<4><<<N3, 256>>>(nullptr, 1, HDIM);
    conv_kernel<<<(HDIM * HDIM) / 1024, 256>>>(W3l, whi, wlo, HDIM * HDIM);
    conv_kernel<<<(HDIM * HDIM) / 1024, 256>>>(W3r, whi + HDIM * HDIM, wlo + HDIM * HDIM,
                                               HDIM * HDIM);
    launch_gemm(N3, HDIM, b3);
    score_kernel<<<(N3 + 7) / 8, 256>>>(p3, N3);
    topk_kernel<<<B_GR, 512>>>(K2_, K3_);
    gate_kernel<<<B_GR * K3_, 256>>>();
    readout_kernel<<<(B_GR * HDIM) / 256, 256>>>(out, K3_);
}

// round 13
// speedup vs baseline: 1.0359x; 1.0358x over previous
#include <cuda_runtime.h>
#include <cuda_bf16.h>
#include <math.h>
#include <float.h>
#include <stdint.h>

// Problem constants
#define B_GR   16
#define NP_    1024
#define FEAT_  512
#define HDIM   1024
#define E_TOT  262144        // 16*1024*16
#define NMAX   16384
#define K1_    820           // ceil(0.8*1024)
#define K2_    656           // ceil(0.8*820)
#define K3_    525           // ceil(0.8*656)
#define SLOT_LG 7            // 128 CSR slots per node (P(deg>127) ~ 1e-60)

// ---------------- device scratch (no allocation allowed) ----------------
__device__ __align__(16) float g_bufA[NMAX * HDIM];   // SAGE output (post-relu)
__device__ __align__(16) float g_bufB[NMAX * HDIM];   // pooled/gated features (fp32)
// bf16 split operand buffers for the MMA GEMM
__device__ __align__(16) __nv_bfloat16 g_ahi[NMAX * HDIM];   // mean-agg hi
__device__ __align__(16) __nv_bfloat16 g_alo[NMAX * HDIM];   // mean-agg lo
__device__ __align__(16) __nv_bfloat16 g_xhi[NMAX * HDIM];   // x / pooled hi
__device__ __align__(16) __nv_bfloat16 g_xlo[NMAX * HDIM];   // x / pooled lo
__device__ __align__(16) __nv_bfloat16 g_whi[2 * HDIM * HDIM];  // [Wl ; Wr] hi
__device__ __align__(16) __nv_bfloat16 g_wlo[2 * HDIM * HDIM];  // [Wl ; Wr] lo

__device__ int   g_src[E_TOT], g_dst[E_TOT], g_valid[E_TOT];
__device__ int   g_csr[NMAX << SLOT_LG];   // fixed-slot CSR: node*128 + pos
__device__ int   g_cnt[NMAX];
__device__ int   g_old[NMAX];
__device__ float g_vals[NMAX];
__device__ int   g_remap[NMAX];
__device__ float g_score[NMAX];

// ---------------- PTX helpers (all sm_80-level, no arch-variant features) --
static __device__ __forceinline__ uint32_t smem_u32(const void* p) {
    uint32_t a;
    asm("{ .reg .u64 t; cvta.to.shared.u64 t, %1; cvt.u32.u64 %0, t; }"
        : "=r"(a) : "l"(p));
    return a;
}

__device__ __forceinline__ void cpa16(uint32_t dst, const void* src, int szbytes) {
    asm volatile("cp.async.cg.shared.global [%0], [%1], 16, %2;"
                 :: "r"(dst), "l"(src), "r"(szbytes));
}
#define CP_COMMIT() asm volatile("cp.async.commit_group;" ::: "memory")
#define CP_WAIT2()  asm volatile("cp.async.wait_group 2;" ::: "memory")

#define LDSM_X4(R, addr) \
    asm volatile("ldmatrix.sync.aligned.m8n8.x4.shared.b16 {%0,%1,%2,%3}, [%4];" \
        : "=r"((R)[0]), "=r"((R)[1]), "=r"((R)[2]), "=r"((R)[3]) : "r"(addr))

#define MMA16816(C, A, B0, B1) \
    asm volatile("mma.sync.aligned.m16n8k16.row.col.f32.bf16.bf16.f32 " \
        "{%0,%1,%2,%3}, {%4,%5,%6,%7}, {%8,%9}, {%0,%1,%2,%3};" \
        : "+f"((C)[0]), "+f"((C)[1]), "+f"((C)[2]), "+f"((C)[3]) \
        : "r"((A)[0]), "r"((A)[1]), "r"((A)[2]), "r"((A)[3]), "r"(B0), "r"(B1))

// swizzled byte offset inside a tile with 64B (32 bf16) rows
__device__ __forceinline__ uint32_t sw64(int r, int c) {
    return (uint32_t)(r * 64 + ((c ^ ((r >> 1) & 3)) << 4));
}

// ---------------- GEMM smem layout ----------------
#define S_AH 0
#define S_AL 8192
#define S_BH 16384
#define S_BL 24576
#define STAGE_SZ 32768
#define NSTAGE 4
#define GEMM_SMEM (NSTAGE * STAGE_SZ)   // 128 KB, 4-stage ring

// ---------------- small utility kernels ----------------
__global__ void zero_cnt_kernel() {
    int i = blockIdx.x * 256 + threadIdx.x;
    if (i < NMAX) g_cnt[i] = 0;
}

// edge init fused with count + direct fixed-slot scatter (g_cnt zeroed first)
__global__ void edge_init_kernel(const int* __restrict__ ei) {
    int e = blockIdx.x * 256 + threadIdx.x;
    int s = ei[e];
    int d = ei[E_TOT + e];
    g_src[e] = s;
    g_dst[e] = d;
    g_valid[e] = 1;
    int pos = atomicAdd(&g_cnt[d], 1);
    g_csr[(d << SLOT_LG) + pos] = s;
}

// remap fused with count + direct scatter into the new graph's fixed-slot CSR
__global__ void edge_remap_kernel() {
    int e = blockIdx.x * 256 + threadIdx.x;
    if (!g_valid[e]) return;
    int s2 = g_remap[g_src[e]];
    int d2 = g_remap[g_dst[e]];
    if (s2 >= 0 && d2 >= 0) {
        g_src[e] = s2; g_dst[e] = d2;
        int pos = atomicAdd(&g_cnt[d2], 1);
        g_csr[(d2 << SLOT_LG) + pos] = s2;
    }
    else g_valid[e] = 0;
}

__device__ __forceinline__ void split_store(float v, __nv_bfloat16* hi, __nv_bfloat16* lo) {
    __nv_bfloat16 h = __float2bfloat16(v);
    *hi = h;
    *lo = __float2bfloat16(v - __bfloat162float(h));
}

// one block (256 threads) per dst node; NF = F/256. Scalar strided loads
// (measured-best: 32 regs, 91% occupancy). 4-way edge unroll for MLP.
template <int NF>
__global__ void aggregate_kernel(const float* __restrict__ xext, int sel, int F) {
    const float* __restrict__ xin = sel ? g_bufB : xext;
    int node = blockIdx.x;
    int c = g_cnt[node];
    int start = node << SLOT_LG;
    float acc[NF];
#pragma unroll
    for (int i = 0; i < NF; i++) acc[i] = 0.0f;
    int e = 0;
    for (; e + 3 < c; e += 4) {
        const float* r0 = xin + (size_t)g_csr[start + e + 0] * F;
        const float* r1 = xin + (size_t)g_csr[start + e + 1] * F;
        const float* r2 = xin + (size_t)g_csr[start + e + 2] * F;
        const float* r3 = xin + (size_t)g_csr[start + e + 3] * F;
        float v0[NF], v1[NF], v2[NF], v3[NF];
#pragma unroll
        for (int i = 0; i < NF; i++) {
            int o = threadIdx.x + i * 256;
            v0[i] = r0[o]; v1[i] = r1[o]; v2[i] = r2[o]; v3[i] = r3[o];
        }
#pragma unroll
        for (int i = 0; i < NF; i++) acc[i] += (v0[i] + v1[i]) + (v2[i] + v3[i]);
    }
    for (; e < c; e++) {
        const float* row = xin + (size_t)g_csr[start + e] * F;
#pragma unroll
        for (int i = 0; i < NF; i++) acc[i] += row[threadIdx.x + i * 256];
    }
    float inv = 1.0f / (float)(c > 1 ? c : 1);
#pragma unroll
    for (int i = 0; i < NF; i++) {
        size_t o = (size_t)node * F + threadIdx.x + i * 256;
        split_store(acc[i] * inv, &g_ahi[o], &g_alo[o]);
    }
}

// fp32 -> bf16 hi/lo conversion (scalar: warp-contiguous 2B stores coalesce)
__global__ void conv_kernel(const float* __restrict__ src,
                            __nv_bfloat16* __restrict__ hi,
                            __nv_bfloat16* __restrict__ lo, int n) {
    int i = blockIdx.x * 256 + threadIdx.x;
    if (i < n) split_store(src[i], &hi[i], &lo[i]);
}

// ---------------- mma.sync fused SAGE GEMM (R4 config) ----------------
__global__ void __launch_bounds__(256, 1)
gemm_mma_kernel(int M, int K, const float* __restrict__ bias) {
    extern __shared__ char smem[];
    const uint32_t sbase = smem_u32(smem);
    const int tid  = threadIdx.x;
    const int lane = tid & 31;
    const int warp = tid >> 5;
    const int warpM = (warp & 3) * 32;
    const int warpN = (warp >> 2) * 64;
    const int row0 = blockIdx.x << 7;
    const int col0 = blockIdx.y << 7;

    const int nchunk = K >> 5;       // k32 chunks per operand source
    const int ntot = nchunk << 1;

    float C[2][8][4];
#pragma unroll
    for (int a = 0; a < 2; a++)
#pragma unroll
        for (int b = 0; b < 8; b++)
#pragma unroll
            for (int d = 0; d < 4; d++) C[a][b][d] = 0.0f;

    auto prefetch = [&](int i) {
        if (i < ntot) {
            int src = (i >= nchunk) ? 1 : 0;
            int k0 = (i - (src ? nchunk : 0)) << 5;
            const __nv_bfloat16* Ah = src ? g_xhi : g_ahi;
            const __nv_bfloat16* Al = src ? g_xlo : g_alo;
            const __nv_bfloat16* Bh = g_whi + (size_t)src * HDIM * K;
            const __nv_bfloat16* Bl = g_wlo + (size_t)src * HDIM * K;
            uint32_t sb = sbase + (uint32_t)(i % NSTAGE) * STAGE_SZ;
#pragma unroll
            for (int u = 0; u < 2; u++) {
                int q = tid + (u << 8);
                int r = q >> 2, c = q & 3;
                uint32_t so = sw64(r, c);
                int gr = row0 + r;
                int ok = (gr < M) ? 16 : 0;
                size_t gro = (size_t)(ok ? gr : 0) * K + k0 + (c << 3);
                cpa16(sb + S_AH + so, Ah + gro, ok);
                cpa16(sb + S_AL + so, Al + gro, ok);
                size_t gco = (size_t)(col0 + r) * K + k0 + (c << 3);
                cpa16(sb + S_BH + so, Bh + gco, 16);
                cpa16(sb + S_BL + so, Bl + gco, 16);
            }
        }
        CP_COMMIT();
    };

    prefetch(0);
    prefetch(1);
    prefetch(2);

    for (int i = 0; i < ntot; i++) {
        CP_WAIT2();
        __syncthreads();
        prefetch(i + 3);

        uint32_t sb = sbase + (uint32_t)(i % NSTAGE) * STAGE_SZ;
#pragma unroll
        for (int kk = 0; kk < 2; kk++) {
            uint32_t ah[2][4], al[2][4];
#pragma unroll
            for (int fm = 0; fm < 2; fm++) {
                int r = warpM + fm * 16 + (lane & 15);
                int c = (kk << 1) + (lane >> 4);
                uint32_t so = sw64(r, c);
                LDSM_X4(ah[fm], sb + S_AH + so);
                LDSM_X4(al[fm], sb + S_AL + so);
            }
            uint32_t bh[4][4], bl[4][4];
#pragma unroll
            for (int fn = 0; fn < 4; fn++) {
                int r = warpN + fn * 16 + ((lane >> 4) << 3) + (lane & 7);
                int c = (kk << 1) + ((lane >> 3) & 1);
                uint32_t so = sw64(r, c);
                LDSM_X4(bh[fn], sb + S_BH + so);
                LDSM_X4(bl[fn], sb + S_BL + so);
            }
#pragma unroll
            for (int t = 0; t < 3; t++) {
#pragma unroll
                for (int fm = 0; fm < 2; fm++)
#pragma unroll
                    for (int fn = 0; fn < 4; fn++)
#pragma unroll
                        for (int g = 0; g < 2; g++) {
                            float* Cp = C[fm][fn * 2 + g];
                            const uint32_t* A = (t == 2) ? al[fm] : ah[fm];
                            const uint32_t* Bq = (t == 1) ? bl[fn] : bh[fn];
                            MMA16816(Cp, A, Bq[g * 2], Bq[g * 2 + 1]);
                        }
            }
        }
    }

    // ---- epilogue: bias + relu, direct stores ----
#pragma unroll
    for (int fm = 0; fm < 2; fm++)
#pragma unroll
        for (int fn = 0; fn < 4; fn++)
#pragma unroll
            for (int g = 0; g < 2; g++) {
                int rb = row0 + warpM + fm * 16 + (lane >> 2);
                int col = col0 + warpN + fn * 16 + g * 8 + ((lane & 3) << 1);
                float2 bb = *(const float2*)(bias + col);
                float* Cp = C[fm][fn * 2 + g];
                if (rb < M) {
                    float2 v;
                    v.x = fmaxf(Cp[0] + bb.x, 0.0f);
                    v.y = fmaxf(Cp[1] + bb.y, 0.0f);
                    *(float2*)(g_bufA + (size_t)rb * HDIM + col) = v;
                }
                if (rb + 8 < M) {
                    float2 v;
                    v.x = fmaxf(Cp[2] + bb.x, 0.0f);
                    v.y = fmaxf(Cp[3] + bb.y, 0.0f);
                    *(float2*)(g_bufA + (size_t)(rb + 8) * HDIM + col) = v;
                }
            }
}

// ---------------- scoring / top-k / pooling ----------------
// one warp per node: s = tanh((h . p)/||p||); ||p|| computed per block (fused)
__global__ void score_kernel(const float* __restrict__ p, int N) {
    __shared__ float sh[8];
    __shared__ float spn;
    int tid = threadIdx.x;
    int lane = tid & 31, wid = tid >> 5;
    float s = 0.0f;
#pragma unroll
    for (int i = tid; i < HDIM; i += 256) s += p[i] * p[i];
#pragma unroll
    for (int o = 16; o; o >>= 1) s += __shfl_xor_sync(0xffffffffu, s, o);
    if (lane == 0) sh[wid] = s;
    __syncthreads();
    if (tid == 0) {
        float t = 0.0f;
#pragma unroll
        for (int i = 0; i < 8; i++) t += sh[i];
        spn = sqrtf(t);
    }
    __syncthreads();

    int node = blockIdx.x * 8 + wid;
    if (node >= N) return;
    const float* row = g_bufA + (size_t)node * HDIM;
    float acc = 0.0f;
#pragma unroll 8
    for (int i = lane; i < HDIM; i += 32) acc += row[i] * p[i];
#pragma unroll
    for (int o = 16; o; o >>= 1) acc += __shfl_xor_sync(0xffffffffu, acc, o);
    if (lane == 0) g_score[node] = tanhf(acc / spn);
}

// one block per graph: bitonic sort 1024 (score,idx) pairs descending
__global__ void topk_kernel(int n_per, int k) {
    __shared__ float ss[1024];
    __shared__ int si[1024];
    int g = blockIdx.x;
    int tid = threadIdx.x;  // 512 threads
    for (int i = tid; i < 1024; i += 512) {
        if (i < n_per) { ss[i] = g_score[g * n_per + i]; si[i] = i; }
        else           { ss[i] = -FLT_MAX;               si[i] = i; }
    }
    __syncthreads();
    for (int ksz = 2; ksz <= 1024; ksz <<= 1) {
        for (int j = ksz >> 1; j > 0; j >>= 1) {
            for (int i = tid; i < 1024; i += 512) {
                int ixj = i ^ j;
                if (ixj > i) {
                    bool dirDesc = ((i & ksz) == 0);
                    float a = ss[i], b = ss[ixj];
                    bool doswap = dirDesc ? (a < b) : (a > b);
                    if (doswap) {
                        ss[i] = b; ss[ixj] = a;
                        int tpi = si[i]; si[i] = si[ixj]; si[ixj] = tpi;
                    }
                }
            }
            __syncthreads();
        }
    }
    for (int r = tid; r < n_per; r += 512) {
        int oldLocal = si[r];
        if (r < k) {
            g_old[g * k + r]  = g * n_per + oldLocal;
            g_vals[g * k + r] = ss[r];
            g_remap[g * n_per + oldLocal] = g * k + r;
        } else {
            g_remap[g * n_per + oldLocal] = -1;
        }
    }
}

// new node i <- old node * score; writes fp32 bufB (+ bf16 hi/lo when emit_split)
__global__ void gate_kernel(int emit_split) {
    int i = blockIdx.x;
    int old = g_old[i];
    float v = g_vals[i];
    const float* srcp = g_bufA + (size_t)old * HDIM;
    float* dstp = g_bufB + (size_t)i * HDIM;
    for (int f = threadIdx.x; f < HDIM; f += 256) {
        float val = srcp[f] * v;
        dstp[f] = val;
        if (emit_split)
            split_store(val, &g_xhi[(size_t)i * HDIM + f], &g_xlo[(size_t)i * HDIM + f]);
    }
}

// out[g, 0:1024] (max) and out[g, 1024:2048] (mean) over bufB.
// ACC=0: overwrite (first layer, removes zero_out). ACC=1: accumulate.
template <int ACC>
__global__ void readout_kernel(float* __restrict__ out, int nper) {
    int gid = blockIdx.x * 256 + threadIdx.x;  // < B*1024
    int g = gid >> 10, f = gid & 1023;
    const float* base = g_bufB + (size_t)g * nper * HDIM + f;
    float mx = -FLT_MAX, sm = 0.0f;
    for (int i = 0; i < nper; i++) {
        float v = base[(size_t)i * HDIM];
        mx = fmaxf(mx, v);
        sm += v;
    }
    if (ACC) {
        out[g * 2048 + f] += mx;
        out[g * 2048 + 1024 + f] += sm / (float)nper;
    } else {
        out[g * 2048 + f] = mx;
        out[g * 2048 + 1024 + f] = sm / (float)nper;
    }
}

// ---------------- host orchestration ----------------
static void launch_gemm(int M, int K, const float* bias) {
    dim3 grid((M + 127) >> 7, HDIM / 128);
    gemm_mma_kernel<<<grid, 256, GEMM_SMEM>>>(M, K, bias);
}

extern "C" void kernel_launch(void* const* d_in, const int* in_sizes, int n_in,
                              void* d_out, int out_size) {
    const float* x  = (const float*)d_in[0];
    const int*   ei = (const int*)d_in[1];
    const float* W1l = (const float*)d_in[3];
    const float* b1  = (const float*)d_in[4];
    const float* W1r = (const float*)d_in[5];
    const float* p1  = (const float*)d_in[6];
    const float* W2l = (const float*)d_in[7];
    const float* b2  = (const float*)d_in[8];
    const float* W2r = (const float*)d_in[9];
    const float* p2  = (const float*)d_in[10];
    const float* W3l = (const float*)d_in[11];
    const float* b3  = (const float*)d_in[12];
    const float* W3r = (const float*)d_in[13];
    const float* p3  = (const float*)d_in[14];
    float* out = (float*)d_out;

    static int s_attr_done = 0;
    if (!s_attr_done) {
        cudaFuncSetAttribute(gemm_mma_kernel,
                             cudaFuncAttributeMaxDynamicSharedMemorySize, GEMM_SMEM);
        s_attr_done = 1;
    }

    const int N1 = B_GR * NP_;   // 16384
    const int N2 = B_GR * K1_;   // 13120
    const int N3 = B_GR * K2_;   // 10496

    __nv_bfloat16 *whi = nullptr, *wlo = nullptr;
    cudaGetSymbolAddress((void**)&whi, g_whi);
    cudaGetSymbolAddress((void**)&wlo, g_wlo);
    __nv_bfloat16 *xhi = nullptr, *xlo = nullptr;
    cudaGetSymbolAddress((void**)&xhi, g_xhi);
    cudaGetSymbolAddress((void**)&xlo, g_xlo);

    // ---------- layer 1 (K = 512) ----------
    zero_cnt_kernel<<<NMAX / 256, 256>>>();
    edge_init_kernel<<<E_TOT / 256, 256>>>(ei);   // init + count + scatter
    aggregate_kernel<2><<<N1, 256>>>(x, 0, FEAT_);
    conv_kernel<<<(N1 * FEAT_) / 256, 256>>>(x, xhi, xlo, N1 * FEAT_);
    conv_kernel<<<(HDIM * FEAT_) / 256, 256>>>(W1l, whi, wlo, HDIM * FEAT_);
    conv_kernel<<<(HDIM * FEAT_) / 256, 256>>>(W1r, whi + HDIM * FEAT_, wlo + HDIM * FEAT_,
                                               HDIM * FEAT_);
    launch_gemm(N1, FEAT_, b1);
    score_kernel<<<N1 / 8, 256>>>(p1, N1);
    topk_kernel<<<B_GR, 512>>>(NP_, K1_);
    gate_kernel<<<N2, 256>>>(1);
    zero_cnt_kernel<<<NMAX / 256, 256>>>();
    edge_remap_kernel<<<E_TOT / 256, 256>>>();    // remap + count + scatter
    readout_kernel<0><<<(B_GR * HDIM) / 256, 256>>>(out, K1_);

    // ---------- layer 2 (K = 1024) ----------
    aggregate_kernel<4><<<N2, 256>>>(nullptr, 1, HDIM);
    conv_kernel<<<(HDIM * HDIM) / 256, 256>>>(W2l, whi, wlo, HDIM * HDIM);
    conv_kernel<<<(HDIM * HDIM) / 256, 256>>>(W2r, whi + HDIM * HDIM, wlo + HDIM * HDIM,
                                              HDIM * HDIM);
    launch_gemm(N2, HDIM, b2);
    score_kernel<<<(N2 + 7) / 8, 256>>>(p2, N2);
    topk_kernel<<<B_GR, 512>>>(K1_, K2_);
    gate_kernel<<<N3, 256>>>(1);
    zero_cnt_kernel<<<NMAX / 256, 256>>>();
    edge_remap_kernel<<<E_TOT / 256, 256>>>();    // remap + count + scatter
    readout_kernel<1><<<(B_GR * HDIM) / 256, 256>>>(out, K2_);

    // ---------- layer 3 (K = 1024) ----------
    aggregate_kernel<4><<<N3, 256>>>(nullptr, 1, HDIM);
    conv_kernel<<<(HDIM * HDIM) / 256, 256>>>(W3l, whi, wlo, HDIM * HDIM);
    conv_kernel<<<(HDIM * HDIM) / 256, 256>>>(W3r, whi + HDIM * HDIM, wlo + HDIM * HDIM,
                                              HDIM * HDIM);
    launch_gemm(N3, HDIM, b3);
    score_kernel<<<(N3 + 7) / 8, 256>>>(p3, N3);
    topk_kernel<<<B_GR, 512>>>(K2_, K3_);
    gate_kernel<<<B_GR * K3_, 256>>>(0);          // final gate: bufB only
    readout_kernel<1><<<(B_GR * HDIM) / 256, 256>>>(out, K3_);
}

// round 14
// speedup vs baseline: 1.0427x; 1.0066x over previous
#include <cuda_runtime.h>
#include <cuda_bf16.h>
#include <math.h>
#include <float.h>
#include <stdint.h>

// Problem constants
#define B_GR   16
#define NP_    1024
#define FEAT_  512
#define HDIM   1024
#define E_TOT  262144        // 16*1024*16
#define NMAX   16384
#define K1_    820           // ceil(0.8*1024)
#define K2_    656           // ceil(0.8*820)
#define K3_    525           // ceil(0.8*656)
#define SLOT_LG 7            // 128 CSR slots per node (P(deg>127) ~ 1e-60)

// ---------------- device scratch (no allocation allowed) ----------------
__device__ __align__(16) float g_bufA[NMAX * HDIM];   // SAGE output (post-relu)
__device__ __align__(16) float g_bufB[NMAX * HDIM];   // pooled/gated features (fp32)
// bf16 split operand buffers for the MMA GEMM
__device__ __align__(16) __nv_bfloat16 g_ahi[NMAX * HDIM];   // mean-agg hi
__device__ __align__(16) __nv_bfloat16 g_alo[NMAX * HDIM];   // mean-agg lo
__device__ __align__(16) __nv_bfloat16 g_xhi[NMAX * HDIM];   // x / pooled hi
__device__ __align__(16) __nv_bfloat16 g_xlo[NMAX * HDIM];   // x / pooled lo
__device__ __align__(16) __nv_bfloat16 g_whi[2 * HDIM * HDIM];  // [Wl ; Wr] hi
__device__ __align__(16) __nv_bfloat16 g_wlo[2 * HDIM * HDIM];  // [Wl ; Wr] lo

__device__ int   g_src[E_TOT], g_dst[E_TOT], g_valid[E_TOT];
__device__ int   g_csr[NMAX << SLOT_LG];   // fixed-slot CSR: node*128 + pos
__device__ int   g_cnt[NMAX];
__device__ int   g_old[NMAX];
__device__ float g_vals[NMAX];
__device__ int   g_remap[NMAX];
__device__ float g_score[NMAX];

// ---------------- PTX helpers (all sm_80-level, no arch-variant features) --
static __device__ __forceinline__ uint32_t smem_u32(const void* p) {
    uint32_t a;
    asm("{ .reg .u64 t; cvta.to.shared.u64 t, %1; cvt.u32.u64 %0, t; }"
        : "=r"(a) : "l"(p));
    return a;
}

__device__ __forceinline__ void cpa16(uint32_t dst, const void* src, int szbytes) {
    asm volatile("cp.async.cg.shared.global [%0], [%1], 16, %2;"
                 :: "r"(dst), "l"(src), "r"(szbytes));
}
#define CP_COMMIT() asm volatile("cp.async.commit_group;" ::: "memory")
#define CP_WAIT2()  asm volatile("cp.async.wait_group 2;" ::: "memory")

#define LDSM_X4(R, addr) \
    asm volatile("ldmatrix.sync.aligned.m8n8.x4.shared.b16 {%0,%1,%2,%3}, [%4];" \
        : "=r"((R)[0]), "=r"((R)[1]), "=r"((R)[2]), "=r"((R)[3]) : "r"(addr))

#define MMA16816(C, A, B0, B1) \
    asm volatile("mma.sync.aligned.m16n8k16.row.col.f32.bf16.bf16.f32 " \
        "{%0,%1,%2,%3}, {%4,%5,%6,%7}, {%8,%9}, {%0,%1,%2,%3};" \
        : "+f"((C)[0]), "+f"((C)[1]), "+f"((C)[2]), "+f"((C)[3]) \
        : "r"((A)[0]), "r"((A)[1]), "r"((A)[2]), "r"((A)[3]), "r"(B0), "r"(B1))

// swizzled byte offset inside a tile with 64B (32 bf16) rows
__device__ __forceinline__ uint32_t sw64(int r, int c) {
    return (uint32_t)(r * 64 + ((c ^ ((r >> 1) & 3)) << 4));
}

// ---------------- GEMM smem layout ----------------
#define S_AH 0
#define S_AL 8192
#define S_BH 16384
#define S_BL 24576
#define STAGE_SZ 32768
#define NSTAGE 4
#define GEMM_SMEM (NSTAGE * STAGE_SZ)   // 128 KB, 4-stage ring

// ---------------- small utility kernels ----------------
__global__ void zero_cnt_kernel() {
    int i = blockIdx.x * 256 + threadIdx.x;
    if (i < NMAX) g_cnt[i] = 0;
}

// edge init fused with count + direct fixed-slot scatter (g_cnt zeroed first)
__global__ void edge_init_kernel(const int* __restrict__ ei) {
    int e = blockIdx.x * 256 + threadIdx.x;
    int s = ei[e];
    int d = ei[E_TOT + e];
    g_src[e] = s;
    g_dst[e] = d;
    g_valid[e] = 1;
    int pos = atomicAdd(&g_cnt[d], 1);
    g_csr[(d << SLOT_LG) + pos] = s;
}

// remap fused with count + direct scatter into the new graph's fixed-slot CSR
__global__ void edge_remap_kernel() {
    int e = blockIdx.x * 256 + threadIdx.x;
    if (!g_valid[e]) return;
    int s2 = g_remap[g_src[e]];
    int d2 = g_remap[g_dst[e]];
    if (s2 >= 0 && d2 >= 0) {
        g_src[e] = s2; g_dst[e] = d2;
        int pos = atomicAdd(&g_cnt[d2], 1);
        g_csr[(d2 << SLOT_LG) + pos] = s2;
    }
    else g_valid[e] = 0;
}

__device__ __forceinline__ void split_store(float v, __nv_bfloat16* hi, __nv_bfloat16* lo) {
    __nv_bfloat16 h = __float2bfloat16(v);
    *hi = h;
    *lo = __float2bfloat16(v - __bfloat162float(h));
}

// one block (256 threads) per dst node; NF = F/256. Scalar strided loads
// (measured-best: 32 regs, 91% occupancy). 4-way edge unroll for MLP.
// CONVX=1: also split-convert this node's own x row into g_xhi/g_xlo
// (fuses the big x conversion pass into the gather kernel).
template <int NF, int CONVX>
__global__ void aggregate_kernel(const float* __restrict__ xext, int sel, int F) {
    const float* __restrict__ xin = sel ? g_bufB : xext;
    int node = blockIdx.x;
    int c = g_cnt[node];
    int start = node << SLOT_LG;
    float acc[NF];
#pragma unroll
    for (int i = 0; i < NF; i++) acc[i] = 0.0f;
    int e = 0;
    for (; e + 3 < c; e += 4) {
        const float* r0 = xin + (size_t)g_csr[start + e + 0] * F;
        const float* r1 = xin + (size_t)g_csr[start + e + 1] * F;
        const float* r2 = xin + (size_t)g_csr[start + e + 2] * F;
        const float* r3 = xin + (size_t)g_csr[start + e + 3] * F;
        float v0[NF], v1[NF], v2[NF], v3[NF];
#pragma unroll
        for (int i = 0; i < NF; i++) {
            int o = threadIdx.x + i * 256;
            v0[i] = r0[o]; v1[i] = r1[o]; v2[i] = r2[o]; v3[i] = r3[o];
        }
#pragma unroll
        for (int i = 0; i < NF; i++) acc[i] += (v0[i] + v1[i]) + (v2[i] + v3[i]);
    }
    for (; e < c; e++) {
        const float* row = xin + (size_t)g_csr[start + e] * F;
#pragma unroll
        for (int i = 0; i < NF; i++) acc[i] += row[threadIdx.x + i * 256];
    }
    float inv = 1.0f / (float)(c > 1 ? c : 1);
#pragma unroll
    for (int i = 0; i < NF; i++) {
        size_t o = (size_t)node * F + threadIdx.x + i * 256;
        split_store(acc[i] * inv, &g_ahi[o], &g_alo[o]);
        if (CONVX) {
            float xv = xext[o];
            split_store(xv, &g_xhi[o], &g_xlo[o]);
        }
    }
}

// fp32 -> bf16 hi/lo for TWO weight matrices in one launch (each n elements)
__global__ void convw_kernel(const float* __restrict__ srcA,
                             const float* __restrict__ srcB,
                             __nv_bfloat16* __restrict__ hi,
                             __nv_bfloat16* __restrict__ lo, int n) {
    int i = blockIdx.x * 256 + threadIdx.x;
    if (i < n) {
        split_store(srcA[i], &hi[i], &lo[i]);
    } else if (i < 2 * n) {
        split_store(srcB[i - n], &hi[i], &lo[i]);
    }
}

// ---------------- mma.sync fused SAGE GEMM (R4 config) ----------------
__global__ void __launch_bounds__(256, 1)
gemm_mma_kernel(int M, int K, const float* __restrict__ bias) {
    extern __shared__ char smem[];
    const uint32_t sbase = smem_u32(smem);
    const int tid  = threadIdx.x;
    const int lane = tid & 31;
    const int warp = tid >> 5;
    const int warpM = (warp & 3) * 32;
    const int warpN = (warp >> 2) * 64;
    const int row0 = blockIdx.x << 7;
    const int col0 = blockIdx.y << 7;

    const int nchunk = K >> 5;       // k32 chunks per operand source
    const int ntot = nchunk << 1;

    float C[2][8][4];
#pragma unroll
    for (int a = 0; a < 2; a++)
#pragma unroll
        for (int b = 0; b < 8; b++)
#pragma unroll
            for (int d = 0; d < 4; d++) C[a][b][d] = 0.0f;

    auto prefetch = [&](int i) {
        if (i < ntot) {
            int src = (i >= nchunk) ? 1 : 0;
            int k0 = (i - (src ? nchunk : 0)) << 5;
            const __nv_bfloat16* Ah = src ? g_xhi : g_ahi;
            const __nv_bfloat16* Al = src ? g_xlo : g_alo;
            const __nv_bfloat16* Bh = g_whi + (size_t)src * HDIM * K;
            const __nv_bfloat16* Bl = g_wlo + (size_t)src * HDIM * K;
            uint32_t sb = sbase + (uint32_t)(i % NSTAGE) * STAGE_SZ;
#pragma unroll
            for (int u = 0; u < 2; u++) {
                int q = tid + (u << 8);
                int r = q >> 2, c = q & 3;
                uint32_t so = sw64(r, c);
                int gr = row0 + r;
                int ok = (gr < M) ? 16 : 0;
                size_t gro = (size_t)(ok ? gr : 0) * K + k0 + (c << 3);
                cpa16(sb + S_AH + so, Ah + gro, ok);
                cpa16(sb + S_AL + so, Al + gro, ok);
                size_t gco = (size_t)(col0 + r) * K + k0 + (c << 3);
                cpa16(sb + S_BH + so, Bh + gco, 16);
                cpa16(sb + S_BL + so, Bl + gco, 16);
            }
        }
        CP_COMMIT();
    };

    prefetch(0);
    prefetch(1);
    prefetch(2);

    for (int i = 0; i < ntot; i++) {
        CP_WAIT2();
        __syncthreads();
        prefetch(i + 3);

        uint32_t sb = sbase + (uint32_t)(i % NSTAGE) * STAGE_SZ;
#pragma unroll
        for (int kk = 0; kk < 2; kk++) {
            uint32_t ah[2][4], al[2][4];
#pragma unroll
            for (int fm = 0; fm < 2; fm++) {
                int r = warpM + fm * 16 + (lane & 15);
                int c = (kk << 1) + (lane >> 4);
                uint32_t so = sw64(r, c);
                LDSM_X4(ah[fm], sb + S_AH + so);
                LDSM_X4(al[fm], sb + S_AL + so);
            }
            uint32_t bh[4][4], bl[4][4];
#pragma unroll
            for (int fn = 0; fn < 4; fn++) {
                int r = warpN + fn * 16 + ((lane >> 4) << 3) + (lane & 7);
                int c = (kk << 1) + ((lane >> 3) & 1);
                uint32_t so = sw64(r, c);
                LDSM_X4(bh[fn], sb + S_BH + so);
                LDSM_X4(bl[fn], sb + S_BL + so);
            }
#pragma unroll
            for (int t = 0; t < 3; t++) {
#pragma unroll
                for (int fm = 0; fm < 2; fm++)
#pragma unroll
                    for (int fn = 0; fn < 4; fn++)
#pragma unroll
                        for (int g = 0; g < 2; g++) {
                            float* Cp = C[fm][fn * 2 + g];
                            const uint32_t* A = (t == 2) ? al[fm] : ah[fm];
                            const uint32_t* Bq = (t == 1) ? bl[fn] : bh[fn];
                            MMA16816(Cp, A, Bq[g * 2], Bq[g * 2 + 1]);
                        }
            }
        }
    }

    // ---- epilogue: bias + relu, direct stores ----
#pragma unroll
    for (int fm = 0; fm < 2; fm++)
#pragma unroll
        for (int fn = 0; fn < 4; fn++)
#pragma unroll
            for (int g = 0; g < 2; g++) {
                int rb = row0 + warpM + fm * 16 + (lane >> 2);
                int col = col0 + warpN + fn * 16 + g * 8 + ((lane & 3) << 1);
                float2 bb = *(const float2*)(bias + col);
                float* Cp = C[fm][fn * 2 + g];
                if (rb < M) {
                    float2 v;
                    v.x = fmaxf(Cp[0] + bb.x, 0.0f);
                    v.y = fmaxf(Cp[1] + bb.y, 0.0f);
                    *(float2*)(g_bufA + (size_t)rb * HDIM + col) = v;
                }
                if (rb + 8 < M) {
                    float2 v;
                    v.x = fmaxf(Cp[2] + bb.x, 0.0f);
                    v.y = fmaxf(Cp[3] + bb.y, 0.0f);
                    *(float2*)(g_bufA + (size_t)(rb + 8) * HDIM + col) = v;
                }
            }
}

// ---------------- scoring / top-k / pooling ----------------
// one warp per node: s = tanh((h . p)/||p||); ||p|| computed per block (fused)
__global__ void score_kernel(const float* __restrict__ p, int N) {
    __shared__ float sh[8];
    __shared__ float spn;
    int tid = threadIdx.x;
    int lane = tid & 31, wid = tid >> 5;
    float s = 0.0f;
#pragma unroll
    for (int i = tid; i < HDIM; i += 256) s += p[i] * p[i];
#pragma unroll
    for (int o = 16; o; o >>= 1) s += __shfl_xor_sync(0xffffffffu, s, o);
    if (lane == 0) sh[wid] = s;
    __syncthreads();
    if (tid == 0) {
        float t = 0.0f;
#pragma unroll
        for (int i = 0; i < 8; i++) t += sh[i];
        spn = sqrtf(t);
    }
    __syncthreads();

    int node = blockIdx.x * 8 + wid;
    if (node >= N) return;
    const float* row = g_bufA + (size_t)node * HDIM;
    float acc = 0.0f;
#pragma unroll 8
    for (int i = lane; i < HDIM; i += 32) acc += row[i] * p[i];
#pragma unroll
    for (int o = 16; o; o >>= 1) acc += __shfl_xor_sync(0xffffffffu, acc, o);
    if (lane == 0) g_score[node] = tanhf(acc / spn);
}

// one block per graph: bitonic sort 1024 (score,idx) pairs descending
__global__ void topk_kernel(int n_per, int k) {
    __shared__ float ss[1024];
    __shared__ int si[1024];
    int g = blockIdx.x;
    int tid = threadIdx.x;  // 512 threads
    for (int i = tid; i < 1024; i += 512) {
        if (i < n_per) { ss[i] = g_score[g * n_per + i]; si[i] = i; }
        else           { ss[i] = -FLT_MAX;               si[i] = i; }
    }
    __syncthreads();
    for (int ksz = 2; ksz <= 1024; ksz <<= 1) {
        for (int j = ksz >> 1; j > 0; j >>= 1) {
            for (int i = tid; i < 1024; i += 512) {
                int ixj = i ^ j;
                if (ixj > i) {
                    bool dirDesc = ((i & ksz) == 0);
                    float a = ss[i], b = ss[ixj];
                    bool doswap = dirDesc ? (a < b) : (a > b);
                    if (doswap) {
                        ss[i] = b; ss[ixj] = a;
                        int tpi = si[i]; si[i] = si[ixj]; si[ixj] = tpi;
                    }
                }
            }
            __syncthreads();
        }
    }
    for (int r = tid; r < n_per; r += 512) {
        int oldLocal = si[r];
        if (r < k) {
            g_old[g * k + r]  = g * n_per + oldLocal;
            g_vals[g * k + r] = ss[r];
            g_remap[g * n_per + oldLocal] = g * k + r;
        } else {
            g_remap[g * n_per + oldLocal] = -1;
        }
    }
}

// new node i <- old node * score; writes fp32 bufB (+ bf16 hi/lo when emit_split)
__global__ void gate_kernel(int emit_split) {
    int i = blockIdx.x;
    int old = g_old[i];
    float v = g_vals[i];
    const float* srcp = g_bufA + (size_t)old * HDIM;
    float* dstp = g_bufB + (size_t)i * HDIM;
    for (int f = threadIdx.x; f < HDIM; f += 256) {
        float val = srcp[f] * v;
        dstp[f] = val;
        if (emit_split)
            split_store(val, &g_xhi[(size_t)i * HDIM + f], &g_xlo[(size_t)i * HDIM + f]);
    }
}

// out[g, 0:1024] (max) and out[g, 1024:2048] (mean) over bufB.
// ACC=0: overwrite (first layer). ACC=1: accumulate.
template <int ACC>
__global__ void readout_kernel(float* __restrict__ out, int nper) {
    int gid = blockIdx.x * 256 + threadIdx.x;  // < B*1024
    int g = gid >> 10, f = gid & 1023;
    const float* base = g_bufB + (size_t)g * nper * HDIM + f;
    float mx = -FLT_MAX, sm = 0.0f;
    for (int i = 0; i < nper; i++) {
        float v = base[(size_t)i * HDIM];
        mx = fmaxf(mx, v);
        sm += v;
    }
    if (ACC) {
        out[g * 2048 + f] += mx;
        out[g * 2048 + 1024 + f] += sm / (float)nper;
    } else {
        out[g * 2048 + f] = mx;
        out[g * 2048 + 1024 + f] = sm / (float)nper;
    }
}

// ---------------- host orchestration ----------------
static void launch_gemm(int M, int K, const float* bias) {
    dim3 grid((M + 127) >> 7, HDIM / 128);
    gemm_mma_kernel<<<grid, 256, GEMM_SMEM>>>(M, K, bias);
}

extern "C" void kernel_launch(void* const* d_in, const int* in_sizes, int n_in,
                              void* d_out, int out_size) {
    const float* x  = (const float*)d_in[0];
    const int*   ei = (const int*)d_in[1];
    const float* W1l = (const float*)d_in[3];
    const float* b1  = (const float*)d_in[4];
    const float* W1r = (const float*)d_in[5];
    const float* p1  = (const float*)d_in[6];
    const float* W2l = (const float*)d_in[7];
    const float* b2  = (const float*)d_in[8];
    const float* W2r = (const float*)d_in[9];
    const float* p2  = (const float*)d_in[10];
    const float* W3l = (const float*)d_in[11];
    const float* b3  = (const float*)d_in[12];
    const float* W3r = (const float*)d_in[13];
    const float* p3  = (const float*)d_in[14];
    float* out = (float*)d_out;

    static int s_attr_done = 0;
    if (!s_attr_done) {
        cudaFuncSetAttribute(gemm_mma_kernel,
                             cudaFuncAttributeMaxDynamicSharedMemorySize, GEMM_SMEM);
        s_attr_done = 1;
    }

    const int N1 = B_GR * NP_;   // 16384
    const int N2 = B_GR * K1_;   // 13120
    const int N3 = B_GR * K2_;   // 10496

    __nv_bfloat16 *whi = nullptr, *wlo = nullptr;
    cudaGetSymbolAddress((void**)&whi, g_whi);
    cudaGetSymbolAddress((void**)&wlo, g_wlo);

    // ---------- layer 1 (K = 512) ----------
    zero_cnt_kernel<<<NMAX / 256, 256>>>();
    edge_init_kernel<<<E_TOT / 256, 256>>>(ei);   // init + count + scatter
    aggregate_kernel<2, 1><<<N1, 256>>>(x, 0, FEAT_);   // gather + x conversion fused
    convw_kernel<<<(2 * HDIM * FEAT_) / 256, 256>>>(W1l, W1r, whi, wlo, HDIM * FEAT_);
    launch_gemm(N1, FEAT_, b1);
    score_kernel<<<N1 / 8, 256>>>(p1, N1);
    topk_kernel<<<B_GR, 512>>>(NP_, K1_);
    gate_kernel<<<N2, 256>>>(1);
    zero_cnt_kernel<<<NMAX / 256, 256>>>();
    edge_remap_kernel<<<E_TOT / 256, 256>>>();    // remap + count + scatter
    readout_kernel<0><<<(B_GR * HDIM) / 256, 256>>>(out, K1_);

    // ---------- layer 2 (K = 1024) ----------
    aggregate_kernel<4, 0><<<N2, 256>>>(nullptr, 1, HDIM);
    convw_kernel<<<(2 * HDIM * HDIM) / 256, 256>>>(W2l, W2r, whi, wlo, HDIM * HDIM);
    launch_gemm(N2, HDIM, b2);
    score_kernel<<<(N2 + 7) / 8, 256>>>(p2, N2);
    topk_kernel<<<B_GR, 512>>>(K1_, K2_);
    gate_kernel<<<N3, 256>>>(1);
    zero_cnt_kernel<<<NMAX / 256, 256>>>();
    edge_remap_kernel<<<E_TOT / 256, 256>>>();    // remap + count + scatter
    readout_kernel<1><<<(B_GR * HDIM) / 256, 256>>>(out, K2_);

    // ---------- layer 3 (K = 1024) ----------
    aggregate_kernel<4, 0><<<N3, 256>>>(nullptr, 1, HDIM);
    convw_kernel<<<(2 * HDIM * HDIM) / 256, 256>>>(W3l, W3r, whi, wlo, HDIM * HDIM);
    launch_gemm(N3, HDIM, b3);
    score_kernel<<<(N3 + 7) / 8, 256>>>(p3, N3);
    topk_kernel<<<B_GR, 512>>>(K2_, K3_);
    gate_kernel<<<B_GR * K3_, 256>>>(0);          // final gate: bufB only
    readout_kernel<1><<<(B_GR * HDIM) / 256, 256>>>(out, K3_);
}

// round 15
// speedup vs baseline: 1.0816x; 1.0373x over previous
#include <cuda_runtime.h>
#include <cuda_bf16.h>
#include <math.h>
#include <float.h>
#include <stdint.h>

// Problem constants
#define B_GR   16
#define NP_    1024
#define FEAT_  512
#define HDIM   1024
#define E_TOT  262144        // 16*1024*16
#define NMAX   16384
#define K1_    820           // ceil(0.8*1024)
#define K2_    656           // ceil(0.8*820)
#define K3_    525           // ceil(0.8*656)
#define SLOT_LG 7            // 128 CSR slots per node (P(deg>127) ~ 1e-60)
#define WTOT   (5 * HDIM * HDIM)   // all-layer weight pool: 1M + 2M + 2M elems

// ---------------- device scratch (no allocation allowed) ----------------
__device__ __align__(16) float g_bufA[NMAX * HDIM];   // SAGE output (post-relu)
__device__ __align__(16) float g_bufB[NMAX * HDIM];   // pooled/gated features (fp32)
// bf16 split operand buffers for the MMA GEMM
__device__ __align__(16) __nv_bfloat16 g_ahi[NMAX * HDIM];   // mean-agg hi
__device__ __align__(16) __nv_bfloat16 g_alo[NMAX * HDIM];   // mean-agg lo
__device__ __align__(16) __nv_bfloat16 g_xhi[NMAX * HDIM];   // x / pooled hi
__device__ __align__(16) __nv_bfloat16 g_xlo[NMAX * HDIM];   // x / pooled lo
__device__ __align__(16) __nv_bfloat16 g_whi[WTOT];   // all layers [Wl;Wr] hi
__device__ __align__(16) __nv_bfloat16 g_wlo[WTOT];   // all layers [Wl;Wr] lo

__device__ int   g_src[E_TOT], g_dst[E_TOT], g_valid[E_TOT];
__device__ int   g_csr[NMAX << SLOT_LG];   // fixed-slot CSR: node*128 + pos
__device__ int   g_cnt[NMAX];
__device__ int   g_old[NMAX];
__device__ float g_vals[NMAX];
__device__ int   g_remap[NMAX];
__device__ float g_score[NMAX];

// ---------------- PTX helpers (all sm_80-level, no arch-variant features) --
static __device__ __forceinline__ uint32_t smem_u32(const void* p) {
    uint32_t a;
    asm("{ .reg .u64 t; cvta.to.shared.u64 t, %1; cvt.u32.u64 %0, t; }"
        : "=r"(a) : "l"(p));
    return a;
}

__device__ __forceinline__ void cpa16(uint32_t dst, const void* src, int szbytes) {
    asm volatile("cp.async.cg.shared.global [%0], [%1], 16, %2;"
                 :: "r"(dst), "l"(src), "r"(szbytes));
}
#define CP_COMMIT() asm volatile("cp.async.commit_group;" ::: "memory")
#define CP_WAIT2()  asm volatile("cp.async.wait_group 2;" ::: "memory")

#define LDSM_X4(R, addr) \
    asm volatile("ldmatrix.sync.aligned.m8n8.x4.shared.b16 {%0,%1,%2,%3}, [%4];" \
        : "=r"((R)[0]), "=r"((R)[1]), "=r"((R)[2]), "=r"((R)[3]) : "r"(addr))

#define MMA16816(C, A, B0, B1) \
    asm volatile("mma.sync.aligned.m16n8k16.row.col.f32.bf16.bf16.f32 " \
        "{%0,%1,%2,%3}, {%4,%5,%6,%7}, {%8,%9}, {%0,%1,%2,%3};" \
        : "+f"((C)[0]), "+f"((C)[1]), "+f"((C)[2]), "+f"((C)[3]) \
        : "r"((A)[0]), "r"((A)[1]), "r"((A)[2]), "r"((A)[3]), "r"(B0), "r"(B1))

// swizzled byte offset inside a tile with 64B (32 bf16) rows
__device__ __forceinline__ uint32_t sw64(int r, int c) {
    return (uint32_t)(r * 64 + ((c ^ ((r >> 1) & 3)) << 4));
}

// ---------------- GEMM smem layout ----------------
#define S_AH 0
#define S_AL 8192
#define S_BH 16384
#define S_BL 24576
#define STAGE_SZ 32768
#define NSTAGE 4
#define GEMM_SMEM (NSTAGE * STAGE_SZ)   // 128 KB, 4-stage ring

// ---------------- small utility kernels ----------------
__global__ void zero_cnt_kernel() {
    int i = blockIdx.x * 256 + threadIdx.x;
    if (i < NMAX) g_cnt[i] = 0;
}

// edge init fused with count + direct fixed-slot scatter (g_cnt zeroed first)
__global__ void edge_init_kernel(const int* __restrict__ ei) {
    int e = blockIdx.x * 256 + threadIdx.x;
    int s = ei[e];
    int d = ei[E_TOT + e];
    g_src[e] = s;
    g_dst[e] = d;
    g_valid[e] = 1;
    int pos = atomicAdd(&g_cnt[d], 1);
    g_csr[(d << SLOT_LG) + pos] = s;
}

// remap fused with count + direct scatter into the new graph's fixed-slot CSR
__global__ void edge_remap_kernel() {
    int e = blockIdx.x * 256 + threadIdx.x;
    if (!g_valid[e]) return;
    int s2 = g_remap[g_src[e]];
    int d2 = g_remap[g_dst[e]];
    if (s2 >= 0 && d2 >= 0) {
        g_src[e] = s2; g_dst[e] = d2;
        int pos = atomicAdd(&g_cnt[d2], 1);
        g_csr[(d2 << SLOT_LG) + pos] = s2;
    }
    else g_valid[e] = 0;
}

__device__ __forceinline__ void split_store(float v, __nv_bfloat16* hi, __nv_bfloat16* lo) {
    __nv_bfloat16 h = __float2bfloat16(v);
    *hi = h;
    *lo = __float2bfloat16(v - __bfloat162float(h));
}

// one block (256 threads) per dst node; NF = F/256. Scalar strided loads
// (measured-best: 32 regs, 91% occupancy). 4-way edge unroll for MLP.
// CONVX=1: also split-convert this node's own x row into g_xhi/g_xlo.
template <int NF, int CONVX>
__global__ void aggregate_kernel(const float* __restrict__ xext, int sel, int F) {
    const float* __restrict__ xin = sel ? g_bufB : xext;
    int node = blockIdx.x;
    int c = g_cnt[node];
    int start = node << SLOT_LG;
    float acc[NF];
#pragma unroll
    for (int i = 0; i < NF; i++) acc[i] = 0.0f;
    int e = 0;
    for (; e + 3 < c; e += 4) {
        const float* r0 = xin + (size_t)g_csr[start + e + 0] * F;
        const float* r1 = xin + (size_t)g_csr[start + e + 1] * F;
        const float* r2 = xin + (size_t)g_csr[start + e + 2] * F;
        const float* r3 = xin + (size_t)g_csr[start + e + 3] * F;
        float v0[NF], v1[NF], v2[NF], v3[NF];
#pragma unroll
        for (int i = 0; i < NF; i++) {
            int o = threadIdx.x + i * 256;
            v0[i] = r0[o]; v1[i] = r1[o]; v2[i] = r2[o]; v3[i] = r3[o];
        }
#pragma unroll
        for (int i = 0; i < NF; i++) acc[i] += (v0[i] + v1[i]) + (v2[i] + v3[i]);
    }
    for (; e < c; e++) {
        const float* row = xin + (size_t)g_csr[start + e] * F;
#pragma unroll
        for (int i = 0; i < NF; i++) acc[i] += row[threadIdx.x + i * 256];
    }
    float inv = 1.0f / (float)(c > 1 ? c : 1);
#pragma unroll
    for (int i = 0; i < NF; i++) {
        size_t o = (size_t)node * F + threadIdx.x + i * 256;
        split_store(acc[i] * inv, &g_ahi[o], &g_alo[o]);
        if (CONVX) {
            float xv = xext[o];
            split_store(xv, &g_xhi[o], &g_xlo[o]);
        }
    }
}

// fp32 -> bf16 hi/lo for TWO weight matrices into pool offset wbase
__global__ void convw_kernel(const float* __restrict__ srcA,
                             const float* __restrict__ srcB,
                             int wbase, int n) {
    int i = blockIdx.x * 256 + threadIdx.x;
    if (i < n) {
        split_store(srcA[i], &g_whi[wbase + i], &g_wlo[wbase + i]);
    } else if (i < 2 * n) {
        split_store(srcB[i - n], &g_whi[wbase + i], &g_wlo[wbase + i]);
    }
}

// ---------------- mma.sync fused SAGE GEMM (R4 config) ----------------
__global__ void __launch_bounds__(256, 1)
gemm_mma_kernel(int M, int K, int wbase, const float* __restrict__ bias) {
    extern __shared__ char smem[];
    const uint32_t sbase = smem_u32(smem);
    const int tid  = threadIdx.x;
    const int lane = tid & 31;
    const int warp = tid >> 5;
    const int warpM = (warp & 3) * 32;
    const int warpN = (warp >> 2) * 64;
    const int row0 = blockIdx.x << 7;
    const int col0 = blockIdx.y << 7;

    const int nchunk = K >> 5;       // k32 chunks per operand source
    const int ntot = nchunk << 1;

    float C[2][8][4];
#pragma unroll
    for (int a = 0; a < 2; a++)
#pragma unroll
        for (int b = 0; b < 8; b++)
#pragma unroll
            for (int d = 0; d < 4; d++) C[a][b][d] = 0.0f;

    auto prefetch = [&](int i) {
        if (i < ntot) {
            int src = (i >= nchunk) ? 1 : 0;
            int k0 = (i - (src ? nchunk : 0)) << 5;
            const __nv_bfloat16* Ah = src ? g_xhi : g_ahi;
            const __nv_bfloat16* Al = src ? g_xlo : g_alo;
            const __nv_bfloat16* Bh = g_whi + wbase + (size_t)src * HDIM * K;
            const __nv_bfloat16* Bl = g_wlo + wbase + (size_t)src * HDIM * K;
            uint32_t sb = sbase + (uint32_t)(i % NSTAGE) * STAGE_SZ;
#pragma unroll
            for (int u = 0; u < 2; u++) {
                int q = tid + (u << 8);
                int r = q >> 2, c = q & 3;
                uint32_t so = sw64(r, c);
                int gr = row0 + r;
                int ok = (gr < M) ? 16 : 0;
                size_t gro = (size_t)(ok ? gr : 0) * K + k0 + (c << 3);
                cpa16(sb + S_AH + so, Ah + gro, ok);
                cpa16(sb + S_AL + so, Al + gro, ok);
                size_t gco = (size_t)(col0 + r) * K + k0 + (c << 3);
                cpa16(sb + S_BH + so, Bh + gco, 16);
                cpa16(sb + S_BL + so, Bl + gco, 16);
            }
        }
        CP_COMMIT();
    };

    prefetch(0);
    prefetch(1);
    prefetch(2);

    for (int i = 0; i < ntot; i++) {
        CP_WAIT2();
        __syncthreads();
        prefetch(i + 3);

        uint32_t sb = sbase + (uint32_t)(i % NSTAGE) * STAGE_SZ;
#pragma unroll
        for (int kk = 0; kk < 2; kk++) {
            uint32_t ah[2][4], al[2][4];
#pragma unroll
            for (int fm = 0; fm < 2; fm++) {
                int r = warpM + fm * 16 + (lane & 15);
                int c = (kk << 1) + (lane >> 4);
                uint32_t so = sw64(r, c);
                LDSM_X4(ah[fm], sb + S_AH + so);
                LDSM_X4(al[fm], sb + S_AL + so);
            }
            uint32_t bh[4][4], bl[4][4];
#pragma unroll
            for (int fn = 0; fn < 4; fn++) {
                int r = warpN + fn * 16 + ((lane >> 4) << 3) + (lane & 7);
                int c = (kk << 1) + ((lane >> 3) & 1);
                uint32_t so = sw64(r, c);
                LDSM_X4(bh[fn], sb + S_BH + so);
                LDSM_X4(bl[fn], sb + S_BL + so);
            }
#pragma unroll
            for (int t = 0; t < 3; t++) {
#pragma unroll
                for (int fm = 0; fm < 2; fm++)
#pragma unroll
                    for (int fn = 0; fn < 4; fn++)
#pragma unroll
                        for (int g = 0; g < 2; g++) {
                            float* Cp = C[fm][fn * 2 + g];
                            const uint32_t* A = (t == 2) ? al[fm] : ah[fm];
                            const uint32_t* Bq = (t == 1) ? bl[fn] : bh[fn];
                            MMA16816(Cp, A, Bq[g * 2], Bq[g * 2 + 1]);
                        }
            }
        }
    }

    // ---- epilogue: bias + relu, direct stores ----
#pragma unroll
    for (int fm = 0; fm < 2; fm++)
#pragma unroll
        for (int fn = 0; fn < 4; fn++)
#pragma unroll
            for (int g = 0; g < 2; g++) {
                int rb = row0 + warpM + fm * 16 + (lane >> 2);
                int col = col0 + warpN + fn * 16 + g * 8 + ((lane & 3) << 1);
                float2 bb = *(const float2*)(bias + col);
                float* Cp = C[fm][fn * 2 + g];
                if (rb < M) {
                    float2 v;
                    v.x = fmaxf(Cp[0] + bb.x, 0.0f);
                    v.y = fmaxf(Cp[1] + bb.y, 0.0f);
                    *(float2*)(g_bufA + (size_t)rb * HDIM + col) = v;
                }
                if (rb + 8 < M) {
                    float2 v;
                    v.x = fmaxf(Cp[2] + bb.x, 0.0f);
                    v.y = fmaxf(Cp[3] + bb.y, 0.0f);
                    *(float2*)(g_bufA + (size_t)(rb + 8) * HDIM + col) = v;
                }
            }
}

// ---------------- scoring / top-k / pooling ----------------
__global__ void score_kernel(const float* __restrict__ p, int N) {
    __shared__ float sh[8];
    __shared__ float spn;
    int tid = threadIdx.x;
    int lane = tid & 31, wid = tid >> 5;
    float s = 0.0f;
#pragma unroll
    for (int i = tid; i < HDIM; i += 256) s += p[i] * p[i];
#pragma unroll
    for (int o = 16; o; o >>= 1) s += __shfl_xor_sync(0xffffffffu, s, o);
    if (lane == 0) sh[wid] = s;
    __syncthreads();
    if (tid == 0) {
        float t = 0.0f;
#pragma unroll
        for (int i = 0; i < 8; i++) t += sh[i];
        spn = sqrtf(t);
    }
    __syncthreads();

    int node = blockIdx.x * 8 + wid;
    if (node >= N) return;
    const float* row = g_bufA + (size_t)node * HDIM;
    float acc = 0.0f;
#pragma unroll 8
    for (int i = lane; i < HDIM; i += 32) acc += row[i] * p[i];
#pragma unroll
    for (int o = 16; o; o >>= 1) acc += __shfl_xor_sync(0xffffffffu, acc, o);
    if (lane == 0) g_score[node] = tanhf(acc / spn);
}

// one block per graph: bitonic sort 1024 (score,idx) pairs descending
__global__ void topk_kernel(int n_per, int k) {
    __shared__ float ss[1024];
    __shared__ int si[1024];
    int g = blockIdx.x;
    int tid = threadIdx.x;  // 512 threads
    for (int i = tid; i < 1024; i += 512) {
        if (i < n_per) { ss[i] = g_score[g * n_per + i]; si[i] = i; }
        else           { ss[i] = -FLT_MAX;               si[i] = i; }
    }
    __syncthreads();
    for (int ksz = 2; ksz <= 1024; ksz <<= 1) {
        for (int j = ksz >> 1; j > 0; j >>= 1) {
            for (int i = tid; i < 1024; i += 512) {
                int ixj = i ^ j;
                if (ixj > i) {
                    bool dirDesc = ((i & ksz) == 0);
                    float a = ss[i], b = ss[ixj];
                    bool doswap = dirDesc ? (a < b) : (a > b);
                    if (doswap) {
                        ss[i] = b; ss[ixj] = a;
                        int tpi = si[i]; si[i] = si[ixj]; si[ixj] = tpi;
                    }
                }
            }
            __syncthreads();
        }
    }
    for (int r = tid; r < n_per; r += 512) {
        int oldLocal = si[r];
        if (r < k) {
            g_old[g * k + r]  = g * n_per + oldLocal;
            g_vals[g * k + r] = ss[r];
            g_remap[g * n_per + oldLocal] = g * k + r;
        } else {
            g_remap[g * n_per + oldLocal] = -1;
        }
    }
}

// new node i <- old node * score; writes fp32 bufB (+ bf16 hi/lo when emit_split)
__global__ void gate_kernel(int emit_split) {
    int i = blockIdx.x;
    int old = g_old[i];
    float v = g_vals[i];
    const float* srcp = g_bufA + (size_t)old * HDIM;
    float* dstp = g_bufB + (size_t)i * HDIM;
    for (int f = threadIdx.x; f < HDIM; f += 256) {
        float val = srcp[f] * v;
        dstp[f] = val;
        if (emit_split)
            split_store(val, &g_xhi[(size_t)i * HDIM + f], &g_xlo[(size_t)i * HDIM + f]);
    }
}

// out[g, 0:1024] (max) and out[g, 1024:2048] (mean) over bufB.
template <int ACC>
__global__ void readout_kernel(float* __restrict__ out, int nper) {
    int gid = blockIdx.x * 256 + threadIdx.x;  // < B*1024
    int g = gid >> 10, f = gid & 1023;
    const float* base = g_bufB + (size_t)g * nper * HDIM + f;
    float mx = -FLT_MAX, sm = 0.0f;
    for (int i = 0; i < nper; i++) {
        float v = base[(size_t)i * HDIM];
        mx = fmaxf(mx, v);
        sm += v;
    }
    if (ACC) {
        out[g * 2048 + f] += mx;
        out[g * 2048 + 1024 + f] += sm / (float)nper;
    } else {
        out[g * 2048 + f] = mx;
        out[g * 2048 + 1024 + f] = sm / (float)nper;
    }
}

// ---------------- host orchestration ----------------
static void launch_gemm(int M, int K, int wbase, const float* bias) {
    dim3 grid((M + 127) >> 7, HDIM / 128);
    gemm_mma_kernel<<<grid, 256, GEMM_SMEM>>>(M, K, wbase, bias);
}

extern "C" void kernel_launch(void* const* d_in, const int* in_sizes, int n_in,
                              void* d_out, int out_size) {
    const float* x  = (const float*)d_in[0];
    const int*   ei = (const int*)d_in[1];
    const float* W1l = (const float*)d_in[3];
    const float* b1  = (const float*)d_in[4];
    const float* W1r = (const float*)d_in[5];
    const float* p1  = (const float*)d_in[6];
    const float* W2l = (const float*)d_in[7];
    const float* b2  = (const float*)d_in[8];
    const float* W2r = (const float*)d_in[9];
    const float* p2  = (const float*)d_in[10];
    const float* W3l = (const float*)d_in[11];
    const float* b3  = (const float*)d_in[12];
    const float* W3r = (const float*)d_in[13];
    const float* p3  = (const float*)d_in[14];
    float* out = (float*)d_out;

    static int s_init = 0;
    static cudaStream_t s2;
    static cudaEvent_t eFork, eW, eG1, eR1, eG2, eR2;
    if (!s_init) {
        cudaFuncSetAttribute(gemm_mma_kernel,
                             cudaFuncAttributeMaxDynamicSharedMemorySize, GEMM_SMEM);
        cudaStreamCreateWithFlags(&s2, cudaStreamNonBlocking);
        cudaEventCreateWithFlags(&eFork, cudaEventDisableTiming);
        cudaEventCreateWithFlags(&eW,    cudaEventDisableTiming);
        cudaEventCreateWithFlags(&eG1,   cudaEventDisableTiming);
        cudaEventCreateWithFlags(&eR1,   cudaEventDisableTiming);
        cudaEventCreateWithFlags(&eG2,   cudaEventDisableTiming);
        cudaEventCreateWithFlags(&eR2,   cudaEventDisableTiming);
        s_init = 1;
    }

    const int N1 = B_GR * NP_;   // 16384
    const int N2 = B_GR * K1_;   // 13120
    const int N3 = B_GR * K2_;   // 10496
    const int WB1 = 0;                       // layer-1 weights: 1M elems
    const int WB2 = 2 * HDIM * FEAT_;        // layer-2 weights: 2M elems
    const int WB3 = WB2 + 2 * HDIM * HDIM;   // layer-3 weights: 2M elems

    // ---- fork: all-layer weight conversion on s2, overlapped with CSR+agg ----
    cudaEventRecord(eFork, 0);
    cudaStreamWaitEvent(s2, eFork, 0);
    convw_kernel<<<(2 * HDIM * FEAT_) / 256, 256, 0, s2>>>(W1l, W1r, WB1, HDIM * FEAT_);
    convw_kernel<<<(2 * HDIM * HDIM) / 256, 256, 0, s2>>>(W2l, W2r, WB2, HDIM * HDIM);
    convw_kernel<<<(2 * HDIM * HDIM) / 256, 256, 0, s2>>>(W3l, W3r, WB3, HDIM * HDIM);
    cudaEventRecord(eW, s2);

    // ---------- layer 1 (K = 512) ----------
    zero_cnt_kernel<<<NMAX / 256, 256>>>();
    edge_init_kernel<<<E_TOT / 256, 256>>>(ei);          // init + count + scatter
    aggregate_kernel<2, 1><<<N1, 256>>>(x, 0, FEAT_);    // gather + x conversion fused
    cudaStreamWaitEvent(0, eW, 0);                       // weights ready
    launch_gemm(N1, FEAT_, WB1, b1);
    score_kernel<<<N1 / 8, 256>>>(p1, N1);
    topk_kernel<<<B_GR, 512>>>(NP_, K1_);
    gate_kernel<<<N2, 256>>>(1);
    cudaEventRecord(eG1, 0);
    // readout L1 on s2, overlapped with layer-2 CSR+aggregate+GEMM
    cudaStreamWaitEvent(s2, eG1, 0);
    readout_kernel<0><<<(B_GR * HDIM) / 256, 256, 0, s2>>>(out, K1_);
    cudaEventRecord(eR1, s2);
    zero_cnt_kernel<<<NMAX / 256, 256>>>();
    edge_remap_kernel<<<E_TOT / 256, 256>>>();           // remap + count + scatter

    // ---------- layer 2 (K = 1024) ----------
    aggregate_kernel<4, 0><<<N2, 256>>>(nullptr, 1, HDIM);
    launch_gemm(N2, HDIM, WB2, b2);
    score_kernel<<<(N2 + 7) / 8, 256>>>(p2, N2);
    topk_kernel<<<B_GR, 512>>>(K1_, K2_);
    cudaStreamWaitEvent(0, eR1, 0);                      // WAR: bufB rewrite below
    gate_kernel<<<N3, 256>>>(1);
    cudaEventRecord(eG2, 0);
    cudaStreamWaitEvent(s2, eG2, 0);
    readout_kernel<1><<<(B_GR * HDIM) / 256, 256, 0, s2>>>(out, K2_);
    cudaEventRecord(eR2, s2);
    zero_cnt_kernel<<<NMAX / 256, 256>>>();
    edge_remap_kernel<<<E_TOT / 256, 256>>>();           // remap + count + scatter

    // ---------- layer 3 (K = 1024) ----------
    aggregate_kernel<4, 0><<<N3, 256>>>(nullptr, 1, HDIM);
    launch_gemm(N3, HDIM, WB3, b3);
    score_kernel<<<(N3 + 7) / 8, 256>>>(p3, N3);
    topk_kernel<<<B_GR, 512>>>(K2_, K3_);
    cudaStreamWaitEvent(0, eR2, 0);                      // WAR: bufB rewrite + out order
    gate_kernel<<<B_GR * K3_, 256>>>(0);                 // final gate: bufB only
    readout_kernel<1><<<(B_GR * HDIM) / 256, 256>>>(out, K3_);
}